// round 1
// baseline (speedup 1.0000x reference)
#include <cuda_runtime.h>
#include <math.h>

#define BB   8
#define SS   4096
#define DD   1024
#define EE   3
#define DD2  2048
#define CL   64          // scan chunk length
#define NCH  64          // number of chunks (SS/CL)
#define EPSV 1e-5f

// ---------------- scratch (device globals; no allocation allowed) ----------
__device__ float g_x   [BB*SS*DD];    // rmsnormed x
__device__ float g_a   [BB*SS*DD];    // gate a = 1-z
__device__ float g_bh  [BB*SS*DD];    // b, overwritten by h in scan phase C
__device__ float g_wg  [BB*DD*DD2];   // mixed W_gh, hid/gate column-interleaved
__device__ float g_wo  [BB*DD*DD];    // mixed W_out
__device__ float g_colsum[BB*DD];     // sum over S of x
__device__ float g_probs [BB*EE];
__device__ float g_cA  [BB*NCH*DD];   // chunk A products
__device__ float g_cB  [BB*NCH*DD];   // chunk B carries -> exclusive carries

__device__ __forceinline__ float sigm(float x) { return 1.0f / (1.0f + __expf(-x)); }

// ---------------- init: zero colsum, write aux_loss --------------------------
__global__ void k_init(float* out, int out_size) {
    int idx = blockIdx.x * 256 + threadIdx.x;
    if (idx < BB * DD) g_colsum[idx] = 0.0f;
    if (idx == 0 && out_size >= BB*SS*DD + BB*DD + 1)
        out[BB*SS*DD + BB*DD] = 0.0f;
}

// ---------------- K1: rmsnorm + column-sum accumulation ----------------------
// grid (SS/64, BB), block 256 (8 warps), each warp handles 8 rows.
__global__ void __launch_bounds__(256) k_rmsnorm(const float* __restrict__ inp,
                                                 const float* __restrict__ normw) {
    int b    = blockIdx.y;
    int t    = threadIdx.x;
    int warp = t >> 5;
    int lane = t & 31;

    __shared__ float sw [DD];
    __shared__ float scs[DD];
    for (int i = t; i < DD; i += 256) { sw[i] = normw[i]; scs[i] = 0.0f; }
    __syncthreads();

    float csum[32];
#pragma unroll
    for (int k = 0; k < 32; k++) csum[k] = 0.0f;

    int s_base = blockIdx.x * 64;
#pragma unroll 1
    for (int r = 0; r < 8; r++) {
        int s = s_base + warp + r * 8;
        const float* row = inp + (size_t)(b * SS + s) * DD;
        float v[32];
        float ss = 0.0f;
#pragma unroll
        for (int k = 0; k < 32; k++) {
            v[k] = row[lane + 32 * k];
            ss += v[k] * v[k];
        }
#pragma unroll
        for (int o = 16; o > 0; o >>= 1) ss += __shfl_xor_sync(0xffffffffu, ss, o);
        float inv = rsqrtf(ss * (1.0f / DD) + EPSV);
        float* xr = g_x + (size_t)(b * SS + s) * DD;
#pragma unroll
        for (int k = 0; k < 32; k++) {
            float xv = v[k] * inv * sw[lane + 32 * k];
            xr[lane + 32 * k] = xv;
            csum[k] += xv;
        }
    }
#pragma unroll
    for (int k = 0; k < 32; k++) atomicAdd(&scs[lane + 32 * k], csum[k]);
    __syncthreads();
    for (int i = t; i < DD; i += 256) atomicAdd(&g_colsum[b * DD + i], scs[i]);
}

// ---------------- K2: router logits + softmax --------------------------------
__global__ void k_router(const float* __restrict__ rw, const float* __restrict__ rb) {
    int b = blockIdx.x, t = threadIdx.x;
    float p0 = 0, p1 = 0, p2 = 0;
    for (int d = t; d < DD; d += 128) {
        float cs = g_colsum[b * DD + d] * (1.0f / SS);
        p0 += cs * rw[d * 3 + 0];
        p1 += cs * rw[d * 3 + 1];
        p2 += cs * rw[d * 3 + 2];
    }
    __shared__ float sm[3][128];
    sm[0][t] = p0; sm[1][t] = p1; sm[2][t] = p2;
    __syncthreads();
    for (int o = 64; o > 0; o >>= 1) {
        if (t < o) {
            sm[0][t] += sm[0][t + o];
            sm[1][t] += sm[1][t + o];
            sm[2][t] += sm[2][t + o];
        }
        __syncthreads();
    }
    if (t == 0) {
        float l0 = sm[0][0] + rb[0], l1 = sm[1][0] + rb[1], l2 = sm[2][0] + rb[2];
        float m  = fmaxf(l0, fmaxf(l1, l2));
        float e0 = __expf(l0 - m), e1 = __expf(l1 - m), e2 = __expf(l2 - m);
        float inv = 1.0f / (e0 + e1 + e2);
        g_probs[b * 3 + 0] = e0 * inv;
        g_probs[b * 3 + 1] = e1 * inv;
        g_probs[b * 3 + 2] = e2 * inv;
    }
}

// ---------------- K3a: mix W_gh with hid/gate column interleave --------------
// output col n: j = n>>1, which = n&1  -> source col which*DD + j
__global__ void k_mixg(const float* __restrict__ wgh) {
    int idx = blockIdx.x * 256 + threadIdx.x;           // over BB*DD*DD2
    int n   = idx & (DD2 - 1);
    int k   = (idx >> 11) & (DD - 1);
    int b   = idx >> 21;
    int col = ((n & 1) ? DD : 0) + (n >> 1);
    size_t base = ((size_t)k) * DD2 + col;
    float acc = g_probs[b * 3 + 0] * wgh[base]
              + g_probs[b * 3 + 1] * wgh[base + (size_t)DD * DD2]
              + g_probs[b * 3 + 2] * wgh[base + (size_t)2 * DD * DD2];
    g_wg[idx] = acc;
}

// ---------------- K3b: mix W_out ---------------------------------------------
__global__ void k_mixo(const float* __restrict__ wout) {
    int idx = blockIdx.x * 256 + threadIdx.x;           // over BB*DD*DD
    int n   = idx & (DD - 1);
    int k   = (idx >> 10) & (DD - 1);
    int b   = idx >> 20;
    size_t base = ((size_t)k) * DD + n;
    float acc = g_probs[b * 3 + 0] * wout[base]
              + g_probs[b * 3 + 1] * wout[base + (size_t)DD * DD]
              + g_probs[b * 3 + 2] * wout[base + (size_t)2 * DD * DD];
    g_wo[idx] = acc;
}

// ---------------- K4: GEMM1 hg = x @ Wg' + gated-elementwise epilogue --------
// 128x128 block tile, BK=8, 8x8 per thread. Writes a,b directly.
__global__ void __launch_bounds__(256) k_gemm1() {
    int b  = blockIdx.z;
    int m0 = blockIdx.y * 128;
    int n0 = blockIdx.x * 128;
    const float* A  = g_x  + (size_t)b * SS * DD;
    const float* Bm = g_wg + (size_t)b * DD * DD2;

    __shared__ float As[8 * 132];
    __shared__ float Bs[8 * 128];

    int t  = threadIdx.x;
    int ty = t >> 4, tx = t & 15;
    int am = t >> 1, ak = (t & 1) * 4;
    int bk = t >> 5, bn = (t & 31) * 4;

    float c[8][8];
#pragma unroll
    for (int i = 0; i < 8; i++)
#pragma unroll
        for (int j = 0; j < 8; j++) c[i][j] = 0.0f;

    for (int kt = 0; kt < DD; kt += 8) {
        float4 av = *(const float4*)(A + (size_t)(m0 + am) * DD + kt + ak);
        float4 bv = *(const float4*)(Bm + (size_t)(kt + bk) * DD2 + n0 + bn);
        As[(ak + 0) * 132 + am] = av.x;
        As[(ak + 1) * 132 + am] = av.y;
        As[(ak + 2) * 132 + am] = av.z;
        As[(ak + 3) * 132 + am] = av.w;
        *(float4*)(Bs + bk * 128 + bn) = bv;
        __syncthreads();
#pragma unroll
        for (int k = 0; k < 8; k++) {
            float4 a0 = *(const float4*)(As + k * 132 + ty * 8);
            float4 a1 = *(const float4*)(As + k * 132 + ty * 8 + 4);
            float4 b0 = *(const float4*)(Bs + k * 128 + tx * 8);
            float4 b1 = *(const float4*)(Bs + k * 128 + tx * 8 + 4);
            float af[8] = {a0.x, a0.y, a0.z, a0.w, a1.x, a1.y, a1.z, a1.w};
            float bf[8] = {b0.x, b0.y, b0.z, b0.w, b1.x, b1.y, b1.z, b1.w};
#pragma unroll
            for (int i = 0; i < 8; i++)
#pragma unroll
                for (int j = 0; j < 8; j++) c[i][j] = fmaf(af[i], bf[j], c[i][j]);
        }
        __syncthreads();
    }

    // epilogue: interleaved (hid,gate) pairs -> a = 1-z, b = z*g(hid)
#pragma unroll
    for (int i = 0; i < 8; i++) {
        int s = m0 + ty * 8 + i;
        size_t row = (size_t)(b * SS + s) * DD;
#pragma unroll
        for (int j2 = 0; j2 < 4; j2++) {
            float hid  = c[i][2 * j2];
            float gate = c[i][2 * j2 + 1];
            float z    = sigm(gate);
            float av   = 1.0f - z;
            float gg   = (hid >= 0.0f) ? (hid + 0.5f) : sigm(hid);
            float bb   = z * gg;
            int jj = (n0 >> 1) + tx * 4 + j2;
            g_a [row + jj] = av;
            g_bh[row + jj] = bb;
        }
    }
}

// ---------------- K5a: scan phase A — per-chunk (A, B) carries ---------------
__global__ void k_scanA(const float* __restrict__ state) {
    int idx = blockIdx.x * 256 + threadIdx.x;       // over BB*NCH*DD
    int d = idx & (DD - 1);
    int c = (idx >> 10) & (NCH - 1);
    int b = idx >> 16;
    size_t base = (size_t)(b * SS + c * CL) * DD + d;
    float A = 1.0f, Bc = 0.0f;
#pragma unroll 8
    for (int s = 0; s < CL; s++) {
        float as = g_a [base + (size_t)s * DD];
        float bs = g_bh[base + (size_t)s * DD];
        if (c == 0 && s == 0) bs += as * state[b * DD + d];
        Bc = fmaf(as, Bc, bs);
        A *= as;
    }
    g_cA[idx] = A;
    g_cB[idx] = Bc;
}

// ---------------- K5b: scan phase B — exclusive carry over chunks ------------
__global__ void k_scanB() {
    int idx = blockIdx.x * 256 + threadIdx.x;       // over BB*DD
    int d = idx & (DD - 1);
    int b = idx >> 10;
    float h = 0.0f;
    for (int c = 0; c < NCH; c++) {
        int off = (b * NCH + c) * DD + d;
        float A  = g_cA[off];
        float Bc = g_cB[off];
        g_cB[off] = h;                 // exclusive incoming h for chunk c
        h = fmaf(A, h, Bc);
    }
}

// ---------------- K5c: scan phase C — apply, write h in place, new_state -----
__global__ void k_scanC(const float* __restrict__ state, float* out, int out_size) {
    int idx = blockIdx.x * 256 + threadIdx.x;       // over BB*NCH*DD
    int d = idx & (DD - 1);
    int c = (idx >> 10) & (NCH - 1);
    int b = idx >> 16;
    size_t base = (size_t)(b * SS + c * CL) * DD + d;
    float h = g_cB[idx];
#pragma unroll 8
    for (int s = 0; s < CL; s++) {
        float as = g_a [base + (size_t)s * DD];
        float bs = g_bh[base + (size_t)s * DD];
        if (c == 0 && s == 0) bs += as * state[b * DD + d];
        h = fmaf(as, h, bs);
        g_bh[base + (size_t)s * DD] = h;
    }
    if (c == NCH - 1 && out_size >= BB*SS*DD + BB*DD)
        out[BB*SS*DD + b * DD + d] = h;
}

// ---------------- K6: GEMM2 out = h @ Wo + inputs ----------------------------
__global__ void __launch_bounds__(256) k_gemm2(const float* __restrict__ inputs,
                                               float* __restrict__ out) {
    int b  = blockIdx.z;
    int m0 = blockIdx.y * 128;
    int n0 = blockIdx.x * 128;
    const float* A  = g_bh + (size_t)b * SS * DD;   // h
    const float* Bm = g_wo + (size_t)b * DD * DD;

    __shared__ float As[8 * 132];
    __shared__ float Bs[8 * 128];

    int t  = threadIdx.x;
    int ty = t >> 4, tx = t & 15;
    int am = t >> 1, ak = (t & 1) * 4;
    int bk = t >> 5, bn = (t & 31) * 4;

    float c[8][8];
#pragma unroll
    for (int i = 0; i < 8; i++)
#pragma unroll
        for (int j = 0; j < 8; j++) c[i][j] = 0.0f;

    for (int kt = 0; kt < DD; kt += 8) {
        float4 av = *(const float4*)(A + (size_t)(m0 + am) * DD + kt + ak);
        float4 bv = *(const float4*)(Bm + (size_t)(kt + bk) * DD + n0 + bn);
        As[(ak + 0) * 132 + am] = av.x;
        As[(ak + 1) * 132 + am] = av.y;
        As[(ak + 2) * 132 + am] = av.z;
        As[(ak + 3) * 132 + am] = av.w;
        *(float4*)(Bs + bk * 128 + bn) = bv;
        __syncthreads();
#pragma unroll
        for (int k = 0; k < 8; k++) {
            float4 a0 = *(const float4*)(As + k * 132 + ty * 8);
            float4 a1 = *(const float4*)(As + k * 132 + ty * 8 + 4);
            float4 b0 = *(const float4*)(Bs + k * 128 + tx * 8);
            float4 b1 = *(const float4*)(Bs + k * 128 + tx * 8 + 4);
            float af[8] = {a0.x, a0.y, a0.z, a0.w, a1.x, a1.y, a1.z, a1.w};
            float bf[8] = {b0.x, b0.y, b0.z, b0.w, b1.x, b1.y, b1.z, b1.w};
#pragma unroll
            for (int i = 0; i < 8; i++)
#pragma unroll
                for (int j = 0; j < 8; j++) c[i][j] = fmaf(af[i], bf[j], c[i][j]);
        }
        __syncthreads();
    }

#pragma unroll
    for (int i = 0; i < 8; i++) {
        int s = m0 + ty * 8 + i;
        size_t off = (size_t)(b * SS + s) * DD + n0 + tx * 8;
        float4 i0 = *(const float4*)(inputs + off);
        float4 i1 = *(const float4*)(inputs + off + 4);
        float4 o0 = make_float4(c[i][0] + i0.x, c[i][1] + i0.y,
                                c[i][2] + i0.z, c[i][3] + i0.w);
        float4 o1 = make_float4(c[i][4] + i1.x, c[i][5] + i1.y,
                                c[i][6] + i1.z, c[i][7] + i1.w);
        *(float4*)(out + off)     = o0;
        *(float4*)(out + off + 4) = o1;
    }
}

// ---------------- launch ------------------------------------------------------
extern "C" void kernel_launch(void* const* d_in, const int* in_sizes, int n_in,
                              void* d_out, int out_size) {
    const float* inputs = (const float*)d_in[0];
    const float* state  = (const float*)d_in[1];
    const float* normw  = (const float*)d_in[2];
    const float* rw     = (const float*)d_in[3];
    const float* rb     = (const float*)d_in[4];
    const float* wgh    = (const float*)d_in[5];
    const float* wout   = (const float*)d_in[6];
    float* out = (float*)d_out;

    k_init   <<<32, 256>>>(out, out_size);
    k_rmsnorm<<<dim3(SS / 64, BB), 256>>>(inputs, normw);
    k_router <<<BB, 128>>>(rw, rb);
    k_mixg   <<<(BB * DD * DD2) / 256, 256>>>(wgh);
    k_mixo   <<<(BB * DD * DD) / 256, 256>>>(wout);
    k_gemm1  <<<dim3(DD2 / 128, SS / 128, BB), 256>>>();
    k_scanA  <<<(BB * NCH * DD) / 256, 256>>>(state);
    k_scanB  <<<(BB * DD) / 256, 256>>>();
    k_scanC  <<<(BB * NCH * DD) / 256, 256>>>(state, out, out_size);
    k_gemm2  <<<dim3(DD / 128, SS / 128, BB), 256>>>(inputs, out);
}

// round 3
// speedup vs baseline: 2.1281x; 2.1281x over previous
#include <cuda_runtime.h>
#include <cuda_bf16.h>
#include <cstdint>
#include <math.h>

#define BB   8
#define SS   4096
#define DD   1024
#define DD2  2048
#define CL   64
#define NCH  64
#define EPSV 1e-5f

// ---------------- scratch (device globals) -----------------------------------
__device__ __nv_bfloat16 g_xh [BB*SS*DD],  g_xl [BB*SS*DD];
__device__ __nv_bfloat16 g_wgh[BB*DD2*DD], g_wgl[BB*DD2*DD];   // mixed Wg^T (interleaved n) hi/lo
__device__ __nv_bfloat16 g_woh[BB*DD*DD],  g_wol[BB*DD*DD];    // mixed Wo^T hi/lo
__device__ __nv_bfloat16 g_hh [BB*SS*DD],  g_hl [BB*SS*DD];
__device__ float g_a[BB*SS*DD], g_b[BB*SS*DD];
__device__ float g_colsum[BB*DD];
__device__ float g_probs [BB*3];
__device__ float g_cA[BB*NCH*DD], g_cB[BB*NCH*DD];

__device__ __forceinline__ float sigm(float x) { return 1.0f / (1.0f + __expf(-x)); }

__device__ __forceinline__ uint32_t cvta_smem(const void* p) {
    uint32_t a;
    asm("{ .reg .u64 t; cvta.to.shared.u64 t, %1; cvt.u32.u64 %0, t; }" : "=r"(a) : "l"(p));
    return a;
}

// ---------------- portable tensor-core primitives ------------------------------
__device__ __forceinline__ void mma16816(float* c, const uint32_t* a, const uint32_t* b) {
    asm volatile(
        "mma.sync.aligned.m16n8k16.row.col.f32.bf16.bf16.f32 "
        "{%0,%1,%2,%3},{%4,%5,%6,%7},{%8,%9},{%0,%1,%2,%3};"
        : "+f"(c[0]), "+f"(c[1]), "+f"(c[2]), "+f"(c[3])
        : "r"(a[0]), "r"(a[1]), "r"(a[2]), "r"(a[3]), "r"(b[0]), "r"(b[1]));
}
__device__ __forceinline__ void ldm4(uint32_t* r, uint32_t a) {
    asm volatile("ldmatrix.sync.aligned.m8n8.x4.shared.b16 {%0,%1,%2,%3}, [%4];"
        : "=r"(r[0]), "=r"(r[1]), "=r"(r[2]), "=r"(r[3]) : "r"(a));
}
#define CPA(s, g) asm volatile("cp.async.cg.shared.global [%0], [%1], 16;" :: "r"(s), "l"(g))
#define CP_COMMIT() asm volatile("cp.async.commit_group;")
#define CP_WAIT1()  asm volatile("cp.async.wait_group 1;")
#define CP_WAIT0()  asm volatile("cp.async.wait_group 0;")

// smem stage layout (80B-padded rows, BK=32 bf16 per row):
// Ah 128x80 | Al 128x80 | Bh 128x80 | Bl 128x80  -> 40960 B per stage, x2 stages
#define MAT_BYTES  10240
#define STAGE_B    40960
#define SMEM_BYTES (2 * STAGE_B)

__device__ __forceinline__ void load_mat(uint32_t sdst, const __nv_bfloat16* g, int tid) {
#pragma unroll
    for (int it = 0; it < 2; it++) {
        int idx = tid + it * 256;
        int r = idx >> 2, cc = idx & 3;
        CPA(sdst + r * 80 + cc * 16, g + (size_t)r * DD + cc * 8);
    }
}

__device__ __forceinline__ void load_stage(uint32_t sbuf,
    const __nv_bfloat16* Ah, const __nv_bfloat16* Al,
    const __nv_bfloat16* Bh, const __nv_bfloat16* Bl, int k0, int tid) {
    load_mat(sbuf,                 Ah + k0, tid);
    load_mat(sbuf + MAT_BYTES,     Al + k0, tid);
    load_mat(sbuf + 2 * MAT_BYTES, Bh + k0, tid);
    load_mat(sbuf + 3 * MAT_BYTES, Bl + k0, tid);
}

// 128x128 tile: c[mf][nf][4], warp grid 2(M) x 4(N), warp tile 64x32.
__device__ __forceinline__ void gemm_mainloop(
    float c[4][4][4], uint32_t sb,
    const __nv_bfloat16* Ah, const __nv_bfloat16* Al,
    const __nv_bfloat16* Bh, const __nv_bfloat16* Bl, int tid) {

    int lane = tid & 31, wid = tid >> 5;
    int wm = wid >> 2, wn = wid & 3;
    uint32_t aoff = (uint32_t)(wm * 64 + (lane & 15)) * 80 + (lane >> 4) * 16;
    uint32_t boff = (uint32_t)(wn * 32 + (lane & 7) + ((lane >> 4) << 3)) * 80
                  + ((lane >> 3) & 1) * 16;

    load_stage(sb, Ah, Al, Bh, Bl, 0, tid);
    CP_COMMIT();

#pragma unroll 1
    for (int s = 0; s < 32; s++) {
        if (s < 31) {
            load_stage(sb + ((s + 1) & 1) * STAGE_B, Ah, Al, Bh, Bl, (s + 1) * 32, tid);
            CP_COMMIT();
            CP_WAIT1();
        } else {
            CP_WAIT0();
        }
        __syncthreads();

        uint32_t base = sb + (s & 1) * STAGE_B;
#pragma unroll
        for (int ks = 0; ks < 2; ks++) {
            uint32_t ah[4][4], al[4][4], bh[2][4], bl[2][4];
#pragma unroll
            for (int mf = 0; mf < 4; mf++) {
                ldm4(ah[mf], base + aoff + mf * (16 * 80) + ks * 32);
                ldm4(al[mf], base + MAT_BYTES + aoff + mf * (16 * 80) + ks * 32);
            }
#pragma unroll
            for (int ng = 0; ng < 2; ng++) {
                ldm4(bh[ng], base + 2 * MAT_BYTES + boff + ng * (16 * 80) + ks * 32);
                ldm4(bl[ng], base + 3 * MAT_BYTES + boff + ng * (16 * 80) + ks * 32);
            }
#pragma unroll
            for (int mf = 0; mf < 4; mf++)
#pragma unroll
                for (int nf = 0; nf < 4; nf++) {
                    int ng = nf >> 1;
                    uint32_t* bhp = &bh[ng][(nf & 1) * 2];
                    uint32_t* blp = &bl[ng][(nf & 1) * 2];
                    mma16816(c[mf][nf], ah[mf], bhp);
                    mma16816(c[mf][nf], al[mf], bhp);
                    mma16816(c[mf][nf], ah[mf], blp);
                }
        }
        __syncthreads();
    }
}

// ---------------- init ----------------------------------------------------------
__global__ void k_init(float* out, int out_size) {
    int idx = blockIdx.x * 256 + threadIdx.x;
    if (idx < BB * DD) g_colsum[idx] = 0.0f;
    if (idx == 0 && out_size >= BB*SS*DD + BB*DD + 1)
        out[BB*SS*DD + BB*DD] = 0.0f;
}

// ---------------- rmsnorm -> bf16 hi/lo + colsum ---------------------------------
__global__ void __launch_bounds__(256) k_rmsnorm(const float* __restrict__ inp,
                                                 const float* __restrict__ normw) {
    int b = blockIdx.y, t = threadIdx.x, warp = t >> 5, lane = t & 31;
    __shared__ float sw[DD];
    __shared__ float scs[DD];
    for (int i = t; i < DD; i += 256) { sw[i] = normw[i]; scs[i] = 0.0f; }
    __syncthreads();
    float csum[32];
#pragma unroll
    for (int k = 0; k < 32; k++) csum[k] = 0.0f;
    int s_base = blockIdx.x * 64;
#pragma unroll 1
    for (int r = 0; r < 8; r++) {
        int s = s_base + warp + r * 8;
        const float* row = inp + (size_t)(b * SS + s) * DD;
        float v[32], ss = 0.0f;
#pragma unroll
        for (int k = 0; k < 32; k++) { v[k] = row[lane + 32 * k]; ss += v[k] * v[k]; }
#pragma unroll
        for (int o = 16; o > 0; o >>= 1) ss += __shfl_xor_sync(0xffffffffu, ss, o);
        float inv = rsqrtf(ss * (1.0f / DD) + EPSV);
        size_t ro = (size_t)(b * SS + s) * DD;
#pragma unroll
        for (int k = 0; k < 32; k++) {
            float xv = v[k] * inv * sw[lane + 32 * k];
            __nv_bfloat16 hi = __float2bfloat16(xv);
            g_xh[ro + lane + 32 * k] = hi;
            g_xl[ro + lane + 32 * k] = __float2bfloat16(xv - __bfloat162float(hi));
            csum[k] += xv;
        }
    }
#pragma unroll
    for (int k = 0; k < 32; k++) atomicAdd(&scs[lane + 32 * k], csum[k]);
    __syncthreads();
    for (int i = t; i < DD; i += 256) atomicAdd(&g_colsum[b * DD + i], scs[i]);
}

// ---------------- router ----------------------------------------------------------
__global__ void k_router(const float* __restrict__ rw, const float* __restrict__ rb) {
    int b = blockIdx.x, t = threadIdx.x;
    float p0 = 0, p1 = 0, p2 = 0;
    for (int d = t; d < DD; d += 128) {
        float cs = g_colsum[b * DD + d] * (1.0f / SS);
        p0 += cs * rw[d * 3 + 0];
        p1 += cs * rw[d * 3 + 1];
        p2 += cs * rw[d * 3 + 2];
    }
    __shared__ float sm[3][128];
    sm[0][t] = p0; sm[1][t] = p1; sm[2][t] = p2;
    __syncthreads();
    for (int o = 64; o > 0; o >>= 1) {
        if (t < o) { sm[0][t] += sm[0][t+o]; sm[1][t] += sm[1][t+o]; sm[2][t] += sm[2][t+o]; }
        __syncthreads();
    }
    if (t == 0) {
        float l0 = sm[0][0] + rb[0], l1 = sm[1][0] + rb[1], l2 = sm[2][0] + rb[2];
        float m = fmaxf(l0, fmaxf(l1, l2));
        float e0 = __expf(l0-m), e1 = __expf(l1-m), e2 = __expf(l2-m);
        float inv = 1.0f / (e0 + e1 + e2);
        g_probs[b*3+0] = e0*inv; g_probs[b*3+1] = e1*inv; g_probs[b*3+2] = e2*inv;
    }
}

// ---------------- mix + transpose Wg (interleaved n = 2j+which) -> bf16 hi/lo ----
__global__ void __launch_bounds__(256) k_mixgT(const float* __restrict__ wgh) {
    int b = blockIdx.z, which = blockIdx.y;
    int jt = blockIdx.x & 31, kt2 = blockIdx.x >> 5;
    int j0 = jt * 32, k0 = kt2 * 32;
    float p0 = g_probs[b*3+0], p1 = g_probs[b*3+1], p2 = g_probs[b*3+2];
    __shared__ float s[32][33];
    int c = threadIdx.x & 31, r = threadIdx.x >> 5;
#pragma unroll
    for (int rr = 0; rr < 4; rr++) {
        int k = k0 + r + 8 * rr;
        size_t o0 = (size_t)k * DD2 + (size_t)which * DD + j0 + c;
        s[r + 8*rr][c] = p0 * wgh[o0] + p1 * wgh[o0 + (size_t)DD*DD2] + p2 * wgh[o0 + (size_t)2*DD*DD2];
    }
    __syncthreads();
#pragma unroll
    for (int rr = 0; rr < 4; rr++) {
        int jl = r + 8 * rr, kl = c;
        float v = s[kl][jl];
        size_t off = ((size_t)b * DD2 + 2*(j0+jl) + which) * DD + k0 + kl;
        __nv_bfloat16 hi = __float2bfloat16(v);
        g_wgh[off] = hi;
        g_wgl[off] = __float2bfloat16(v - __bfloat162float(hi));
    }
}

// ---------------- mix + transpose Wo -> bf16 hi/lo --------------------------------
__global__ void __launch_bounds__(256) k_mixoT(const float* __restrict__ wout) {
    int b = blockIdx.z;
    int jt = blockIdx.x & 31, kt2 = blockIdx.x >> 5;
    int j0 = jt * 32, k0 = kt2 * 32;
    float p0 = g_probs[b*3+0], p1 = g_probs[b*3+1], p2 = g_probs[b*3+2];
    __shared__ float s[32][33];
    int c = threadIdx.x & 31, r = threadIdx.x >> 5;
#pragma unroll
    for (int rr = 0; rr < 4; rr++) {
        int k = k0 + r + 8 * rr;
        size_t o0 = (size_t)k * DD + j0 + c;
        s[r + 8*rr][c] = p0 * wout[o0] + p1 * wout[o0 + (size_t)DD*DD] + p2 * wout[o0 + (size_t)2*DD*DD];
    }
    __syncthreads();
#pragma unroll
    for (int rr = 0; rr < 4; rr++) {
        int jl = r + 8 * rr, kl = c;
        float v = s[kl][jl];
        size_t off = ((size_t)b * DD + j0 + jl) * DD + k0 + kl;
        __nv_bfloat16 hi = __float2bfloat16(v);
        g_woh[off] = hi;
        g_wol[off] = __float2bfloat16(v - __bfloat162float(hi));
    }
}

// ---------------- GEMM1: hg = x @ Wg^T, epilogue -> a,b ----------------------------
__global__ void __launch_bounds__(256, 1) k_gemm1() {
    extern __shared__ __align__(128) char smraw[];
    uint32_t sb = cvta_smem(smraw);
    int tid = threadIdx.x;
    int b = blockIdx.z, m0 = blockIdx.y * 128, n0 = blockIdx.x * 128;

    const __nv_bfloat16* Ah = g_xh  + ((size_t)b * SS  + m0) * DD;
    const __nv_bfloat16* Al = g_xl  + ((size_t)b * SS  + m0) * DD;
    const __nv_bfloat16* Bh = g_wgh + ((size_t)b * DD2 + n0) * DD;
    const __nv_bfloat16* Bl = g_wgl + ((size_t)b * DD2 + n0) * DD;

    float c[4][4][4];
#pragma unroll
    for (int i = 0; i < 4; i++)
#pragma unroll
        for (int j = 0; j < 4; j++)
#pragma unroll
            for (int k = 0; k < 4; k++) c[i][j][k] = 0.0f;

    gemm_mainloop(c, sb, Ah, Al, Bh, Bl, tid);

    int lane = tid & 31, wid = tid >> 5;
    int wm = wid >> 2, wn = wid & 3;
    int rbase = m0 + wm * 64 + (lane >> 2);
    int jbase = (n0 >> 1) + wn * 16 + (lane & 3);
#pragma unroll
    for (int mf = 0; mf < 4; mf++)
#pragma unroll
        for (int nf = 0; nf < 4; nf++)
#pragma unroll
            for (int hh = 0; hh < 2; hh++) {
                float hid  = c[mf][nf][hh * 2];
                float gate = c[mf][nf][hh * 2 + 1];
                float z  = sigm(gate);
                float gg = (hid >= 0.0f) ? (hid + 0.5f) : sigm(hid);
                int row = rbase + mf * 16 + hh * 8;
                int j   = jbase + nf * 4;
                size_t off = ((size_t)b * SS + row) * DD + j;
                g_a[off] = 1.0f - z;
                g_b[off] = z * gg;
            }
}

// ---------------- GEMM2: out = h @ Wo^T + inputs ------------------------------------
__global__ void __launch_bounds__(256, 1) k_gemm2(const float* __restrict__ inputs,
                                                  float* __restrict__ out) {
    extern __shared__ __align__(128) char smraw[];
    uint32_t sb = cvta_smem(smraw);
    int tid = threadIdx.x;
    int b = blockIdx.z, m0 = blockIdx.y * 128, n0 = blockIdx.x * 128;

    const __nv_bfloat16* Ah = g_hh  + ((size_t)b * SS + m0) * DD;
    const __nv_bfloat16* Al = g_hl  + ((size_t)b * SS + m0) * DD;
    const __nv_bfloat16* Bh = g_woh + ((size_t)b * DD + n0) * DD;
    const __nv_bfloat16* Bl = g_wol + ((size_t)b * DD + n0) * DD;

    float c[4][4][4];
#pragma unroll
    for (int i = 0; i < 4; i++)
#pragma unroll
        for (int j = 0; j < 4; j++)
#pragma unroll
            for (int k = 0; k < 4; k++) c[i][j][k] = 0.0f;

    gemm_mainloop(c, sb, Ah, Al, Bh, Bl, tid);

    int lane = tid & 31, wid = tid >> 5;
    int wm = wid >> 2, wn = wid & 3;
    int rbase = m0 + wm * 64 + (lane >> 2);
    int cbase = n0 + wn * 32 + (lane & 3) * 2;
#pragma unroll
    for (int mf = 0; mf < 4; mf++)
#pragma unroll
        for (int nf = 0; nf < 4; nf++)
#pragma unroll
            for (int hh = 0; hh < 2; hh++) {
                int row = rbase + mf * 16 + hh * 8;
                int col = cbase + nf * 8;
                size_t off = ((size_t)b * SS + row) * DD + col;
                float2 iv = *(const float2*)&inputs[off];
                float2 ov;
                ov.x = c[mf][nf][hh * 2]     + iv.x;
                ov.y = c[mf][nf][hh * 2 + 1] + iv.y;
                *(float2*)&out[off] = ov;
            }
}

// ---------------- scan ----------------------------------------------------------------
__global__ void k_scanA(const float* __restrict__ state) {
    int idx = blockIdx.x * 256 + threadIdx.x;
    int d = idx & (DD - 1);
    int c = (idx >> 10) & (NCH - 1);
    int b = idx >> 16;
    size_t base = (size_t)(b * SS + c * CL) * DD + d;
    float A = 1.0f, Bc = 0.0f;
#pragma unroll 8
    for (int s = 0; s < CL; s++) {
        float as = g_a[base + (size_t)s * DD];
        float bs = g_b[base + (size_t)s * DD];
        if (c == 0 && s == 0) bs += as * state[b * DD + d];
        Bc = fmaf(as, Bc, bs);
        A *= as;
    }
    g_cA[idx] = A;
    g_cB[idx] = Bc;
}

__global__ void k_scanB() {
    int idx = blockIdx.x * 256 + threadIdx.x;
    int d = idx & (DD - 1);
    int b = idx >> 10;
    float h = 0.0f;
    for (int c = 0; c < NCH; c++) {
        int off = (b * NCH + c) * DD + d;
        float A = g_cA[off], Bc = g_cB[off];
        g_cB[off] = h;
        h = fmaf(A, h, Bc);
    }
}

__global__ void k_scanC(const float* __restrict__ state, float* out, int out_size) {
    int idx = blockIdx.x * 256 + threadIdx.x;
    int d = idx & (DD - 1);
    int c = (idx >> 10) & (NCH - 1);
    int b = idx >> 16;
    size_t base = (size_t)(b * SS + c * CL) * DD + d;
    float h = g_cB[idx];
#pragma unroll 8
    for (int s = 0; s < CL; s++) {
        float as = g_a[base + (size_t)s * DD];
        float bs = g_b[base + (size_t)s * DD];
        if (c == 0 && s == 0) bs += as * state[b * DD + d];
        h = fmaf(as, h, bs);
        __nv_bfloat16 hi = __float2bfloat16(h);
        g_hh[base + (size_t)s * DD] = hi;
        g_hl[base + (size_t)s * DD] = __float2bfloat16(h - __bfloat162float(hi));
    }
    if (c == NCH - 1 && out_size >= BB*SS*DD + BB*DD)
        out[BB*SS*DD + b * DD + d] = h;
}

// ---------------- launch ------------------------------------------------------------
extern "C" void kernel_launch(void* const* d_in, const int* in_sizes, int n_in,
                              void* d_out, int out_size) {
    const float* inputs = (const float*)d_in[0];
    const float* state  = (const float*)d_in[1];
    const float* normw  = (const float*)d_in[2];
    const float* rw     = (const float*)d_in[3];
    const float* rb     = (const float*)d_in[4];
    const float* wgh    = (const float*)d_in[5];
    const float* wout   = (const float*)d_in[6];
    float* out = (float*)d_out;

    cudaFuncSetAttribute(k_gemm1, cudaFuncAttributeMaxDynamicSharedMemorySize, SMEM_BYTES);
    cudaFuncSetAttribute(k_gemm2, cudaFuncAttributeMaxDynamicSharedMemorySize, SMEM_BYTES);

    k_init   <<<32, 256>>>(out, out_size);
    k_rmsnorm<<<dim3(SS / 64, BB), 256>>>(inputs, normw);
    k_router <<<BB, 128>>>(rw, rb);
    k_mixgT  <<<dim3(1024, 2, BB), 256>>>(wgh);
    k_mixoT  <<<dim3(1024, 1, BB), 256>>>(wout);
    k_gemm1  <<<dim3(DD2 / 128, SS / 128, BB), 256, SMEM_BYTES>>>();
    k_scanA  <<<(BB * NCH * DD) / 256, 256>>>(state);
    k_scanB  <<<(BB * DD) / 256, 256>>>();
    k_scanC  <<<(BB * NCH * DD) / 256, 256>>>(state, out, out_size);
    k_gemm2  <<<dim3(DD / 128, SS / 128, BB), 256, SMEM_BYTES>>>(inputs, out);
}

// round 4
// speedup vs baseline: 2.7641x; 1.2988x over previous
#include <cuda_runtime.h>
#include <cuda_fp16.h>
#include <cstdint>
#include <math.h>

#define BB   8
#define SS   4096
#define DD   1024
#define DD2  2048
#define CL   64
#define NCH  64
#define EPSV 1e-5f

// ---------------- scratch (device globals) -----------------------------------
__device__ __half g_xh[BB*SS*DD], g_xl[BB*SS*DD];   // rmsnorm x hi/lo fp16
__device__ __half g_wg[BB*DD2*DD];                  // mixed Wg^T (interleaved n) fp16
__device__ __half g_wo[BB*DD*DD];                   // mixed Wo^T fp16
__device__ __half g_hh[BB*SS*DD], g_hl[BB*SS*DD];   // scan h hi/lo fp16
__device__ float g_a[BB*SS*DD], g_b[BB*SS*DD];
__device__ float g_colsum[BB*DD];
__device__ float g_probs [BB*3];
__device__ float g_cA[BB*NCH*DD], g_cB[BB*NCH*DD];

__device__ __forceinline__ float sigm(float x) { return 1.0f / (1.0f + __expf(-x)); }

__device__ __forceinline__ uint32_t cvta_smem(const void* p) {
    uint32_t a;
    asm("{ .reg .u64 t; cvta.to.shared.u64 t, %1; cvt.u32.u64 %0, t; }" : "=r"(a) : "l"(p));
    return a;
}

// ---------------- portable tensor-core primitives ------------------------------
__device__ __forceinline__ void mma16816(float* c, const uint32_t* a, const uint32_t* b) {
    asm volatile(
        "mma.sync.aligned.m16n8k16.row.col.f32.f16.f16.f32 "
        "{%0,%1,%2,%3},{%4,%5,%6,%7},{%8,%9},{%0,%1,%2,%3};"
        : "+f"(c[0]), "+f"(c[1]), "+f"(c[2]), "+f"(c[3])
        : "r"(a[0]), "r"(a[1]), "r"(a[2]), "r"(a[3]), "r"(b[0]), "r"(b[1]));
}
__device__ __forceinline__ void ldm4(uint32_t* r, uint32_t a) {
    asm volatile("ldmatrix.sync.aligned.m8n8.x4.shared.b16 {%0,%1,%2,%3}, [%4];"
        : "=r"(r[0]), "=r"(r[1]), "=r"(r[2]), "=r"(r[3]) : "r"(a));
}
#define CPA(s, g) asm volatile("cp.async.cg.shared.global [%0], [%1], 16;" :: "r"(s), "l"(g))
#define CP_COMMIT() asm volatile("cp.async.commit_group;")
#define CP_WAIT1()  asm volatile("cp.async.wait_group 1;")
#define CP_WAIT0()  asm volatile("cp.async.wait_group 0;")

// smem stage: Ah 128x80 | Al 128x80 | Bh 128x80  (BK=32 fp16 = 64B + 16B pad)
#define MAT_BYTES  10240
#define STAGE_B    30720
#define SMEM_BYTES 92160          // 3 stages; also covers epilogue staging (68KB)

__device__ __forceinline__ void load_mat(uint32_t sdst, const __half* g, int tid) {
#pragma unroll
    for (int it = 0; it < 2; it++) {
        int idx = tid + it * 256;
        int r = idx >> 2, cc = idx & 3;
        CPA(sdst + r * 80 + cc * 16, g + (size_t)r * DD + cc * 8);
    }
}
__device__ __forceinline__ void load_stage(uint32_t sbuf,
    const __half* Ah, const __half* Al, const __half* Bh, int k0, int tid) {
    load_mat(sbuf,                 Ah + k0, tid);
    load_mat(sbuf + MAT_BYTES,     Al + k0, tid);
    load_mat(sbuf + 2 * MAT_BYTES, Bh + k0, tid);
}

// 128x128 tile, 8 warps (2M x 4N), warp tile 64x32; 2-term compensated fp16.
__device__ __forceinline__ void gemm_mainloop(
    float c[4][4][4], uint32_t sb,
    const __half* Ah, const __half* Al, const __half* Bh, int tid) {

    int lane = tid & 31, wid = tid >> 5;
    int wm = wid >> 2, wn = wid & 3;
    uint32_t aoff = (uint32_t)(wm * 64 + (lane & 15)) * 80 + (lane >> 4) * 16;
    uint32_t boff = (uint32_t)(wn * 32 + (lane & 7) + ((lane >> 4) << 3)) * 80
                  + ((lane >> 3) & 1) * 16;

    load_stage(sb, Ah, Al, Bh, 0, tid);
    CP_COMMIT();
    load_stage(sb + STAGE_B, Ah, Al, Bh, 32, tid);
    CP_COMMIT();

#pragma unroll 1
    for (int s = 0; s < 32; s++) {
        if (s < 31) CP_WAIT1(); else CP_WAIT0();
        __syncthreads();
        if (s < 30) {
            int nb = (s + 2) % 3;
            load_stage(sb + nb * STAGE_B, Ah, Al, Bh, (s + 2) * 32, tid);
            CP_COMMIT();
        }
        uint32_t base = sb + (s % 3) * STAGE_B;
#pragma unroll
        for (int ks = 0; ks < 2; ks++) {
            uint32_t ah[4][4], al[4][4], bh[2][4];
#pragma unroll
            for (int mf = 0; mf < 4; mf++) {
                ldm4(ah[mf], base + aoff + mf * (16 * 80) + ks * 32);
                ldm4(al[mf], base + MAT_BYTES + aoff + mf * (16 * 80) + ks * 32);
            }
#pragma unroll
            for (int ng = 0; ng < 2; ng++)
                ldm4(bh[ng], base + 2 * MAT_BYTES + boff + ng * (16 * 80) + ks * 32);
#pragma unroll
            for (int mf = 0; mf < 4; mf++)
#pragma unroll
                for (int nf = 0; nf < 4; nf++) {
                    uint32_t* bhp = &bh[nf >> 1][(nf & 1) * 2];
                    mma16816(c[mf][nf], ah[mf], bhp);
                    mma16816(c[mf][nf], al[mf], bhp);
                }
        }
    }
    __syncthreads();
}

// ---------------- init ----------------------------------------------------------
__global__ void k_init(float* out, int out_size) {
    int idx = blockIdx.x * 256 + threadIdx.x;
    if (idx < BB * DD) g_colsum[idx] = 0.0f;
    if (idx == 0 && out_size >= BB*SS*DD + BB*DD + 1)
        out[BB*SS*DD + BB*DD] = 0.0f;
}

// ---------------- rmsnorm -> fp16 hi/lo + colsum ---------------------------------
__global__ void __launch_bounds__(256) k_rmsnorm(const float* __restrict__ inp,
                                                 const float* __restrict__ normw) {
    int b = blockIdx.y, t = threadIdx.x, warp = t >> 5, lane = t & 31;
    __shared__ float sw[DD];
    __shared__ float scs[DD];
    for (int i = t; i < DD; i += 256) { sw[i] = normw[i]; scs[i] = 0.0f; }
    __syncthreads();
    float csum[32];
#pragma unroll
    for (int k = 0; k < 32; k++) csum[k] = 0.0f;
    int s_base = blockIdx.x * 64;
#pragma unroll 1
    for (int r = 0; r < 8; r++) {
        int s = s_base + warp + r * 8;
        const float* row = inp + (size_t)(b * SS + s) * DD;
        float v[32], ss = 0.0f;
#pragma unroll
        for (int k = 0; k < 32; k++) { v[k] = row[lane + 32 * k]; ss += v[k] * v[k]; }
#pragma unroll
        for (int o = 16; o > 0; o >>= 1) ss += __shfl_xor_sync(0xffffffffu, ss, o);
        float inv = rsqrtf(ss * (1.0f / DD) + EPSV);
        size_t ro = (size_t)(b * SS + s) * DD;
#pragma unroll
        for (int k = 0; k < 32; k++) {
            float xv = v[k] * inv * sw[lane + 32 * k];
            __half hi = __float2half_rn(xv);
            g_xh[ro + lane + 32 * k] = hi;
            g_xl[ro + lane + 32 * k] = __float2half_rn(xv - __half2float(hi));
            csum[k] += xv;
        }
    }
#pragma unroll
    for (int k = 0; k < 32; k++) atomicAdd(&scs[lane + 32 * k], csum[k]);
    __syncthreads();
    for (int i = t; i < DD; i += 256) atomicAdd(&g_colsum[b * DD + i], scs[i]);
}

// ---------------- router ----------------------------------------------------------
__global__ void k_router(const float* __restrict__ rw, const float* __restrict__ rb) {
    int b = blockIdx.x, t = threadIdx.x;
    float p0 = 0, p1 = 0, p2 = 0;
    for (int d = t; d < DD; d += 128) {
        float cs = g_colsum[b * DD + d] * (1.0f / SS);
        p0 += cs * rw[d * 3 + 0];
        p1 += cs * rw[d * 3 + 1];
        p2 += cs * rw[d * 3 + 2];
    }
    __shared__ float sm[3][128];
    sm[0][t] = p0; sm[1][t] = p1; sm[2][t] = p2;
    __syncthreads();
    for (int o = 64; o > 0; o >>= 1) {
        if (t < o) { sm[0][t] += sm[0][t+o]; sm[1][t] += sm[1][t+o]; sm[2][t] += sm[2][t+o]; }
        __syncthreads();
    }
    if (t == 0) {
        float l0 = sm[0][0] + rb[0], l1 = sm[1][0] + rb[1], l2 = sm[2][0] + rb[2];
        float m = fmaxf(l0, fmaxf(l1, l2));
        float e0 = __expf(l0-m), e1 = __expf(l1-m), e2 = __expf(l2-m);
        float inv = 1.0f / (e0 + e1 + e2);
        g_probs[b*3+0] = e0*inv; g_probs[b*3+1] = e1*inv; g_probs[b*3+2] = e2*inv;
    }
}

// ---------------- mix + transpose Wg (interleaved n = 2j+which) -> fp16 ----------
__global__ void __launch_bounds__(256) k_mixgT(const float* __restrict__ wgh) {
    int b = blockIdx.z, which = blockIdx.y;
    int jt = blockIdx.x & 31, kt2 = blockIdx.x >> 5;
    int j0 = jt * 32, k0 = kt2 * 32;
    float p0 = g_probs[b*3+0], p1 = g_probs[b*3+1], p2 = g_probs[b*3+2];
    __shared__ float s[32][33];
    int c = threadIdx.x & 31, r = threadIdx.x >> 5;
#pragma unroll
    for (int rr = 0; rr < 4; rr++) {
        int k = k0 + r + 8 * rr;
        size_t o0 = (size_t)k * DD2 + (size_t)which * DD + j0 + c;
        s[r + 8*rr][c] = p0 * wgh[o0] + p1 * wgh[o0 + (size_t)DD*DD2] + p2 * wgh[o0 + (size_t)2*DD*DD2];
    }
    __syncthreads();
#pragma unroll
    for (int rr = 0; rr < 4; rr++) {
        int jl = r + 8 * rr, kl = c;
        size_t off = ((size_t)b * DD2 + 2*(j0+jl) + which) * DD + k0 + kl;
        g_wg[off] = __float2half_rn(s[kl][jl]);
    }
}

// ---------------- mix + transpose Wo -> fp16 --------------------------------------
__global__ void __launch_bounds__(256) k_mixoT(const float* __restrict__ wout) {
    int b = blockIdx.z;
    int jt = blockIdx.x & 31, kt2 = blockIdx.x >> 5;
    int j0 = jt * 32, k0 = kt2 * 32;
    float p0 = g_probs[b*3+0], p1 = g_probs[b*3+1], p2 = g_probs[b*3+2];
    __shared__ float s[32][33];
    int c = threadIdx.x & 31, r = threadIdx.x >> 5;
#pragma unroll
    for (int rr = 0; rr < 4; rr++) {
        int k = k0 + r + 8 * rr;
        size_t o0 = (size_t)k * DD + j0 + c;
        s[r + 8*rr][c] = p0 * wout[o0] + p1 * wout[o0 + (size_t)DD*DD] + p2 * wout[o0 + (size_t)2*DD*DD];
    }
    __syncthreads();
#pragma unroll
    for (int rr = 0; rr < 4; rr++) {
        int jl = r + 8 * rr, kl = c;
        size_t off = ((size_t)b * DD + j0 + jl) * DD + k0 + kl;
        g_wo[off] = __float2half_rn(s[kl][jl]);
    }
}

// ---------------- GEMM1: hg = x @ Wg^T, epilogue -> a,b (smem-staged) -------------
__global__ void __launch_bounds__(256, 1) k_gemm1() {
    extern __shared__ __align__(128) char smraw[];
    uint32_t sb = cvta_smem(smraw);
    int tid = threadIdx.x;
    int b = blockIdx.z, m0 = blockIdx.y * 128, n0 = blockIdx.x * 128;

    const __half* Ah = g_xh + ((size_t)b * SS  + m0) * DD;
    const __half* Al = g_xl + ((size_t)b * SS  + m0) * DD;
    const __half* Bh = g_wg + ((size_t)b * DD2 + n0) * DD;

    float c[4][4][4];
#pragma unroll
    for (int i = 0; i < 4; i++)
#pragma unroll
        for (int j = 0; j < 4; j++)
#pragma unroll
            for (int k = 0; k < 4; k++) c[i][j][k] = 0.0f;

    gemm_mainloop(c, sb, Ah, Al, Bh, tid);

    // stage a,b into padded smem (pitch 68 floats -> conflict-free), then coalesced write
    float* sa = (float*)smraw;            // 128 x 68 floats = 34816 B
    float* sbb = sa + 128 * 68;           // second array
    int lane = tid & 31, wid = tid >> 5;
    int wm = wid >> 2, wn = wid & 3;
    int rloc = wm * 64 + (lane >> 2);
    int jloc = wn * 16 + (lane & 3);
#pragma unroll
    for (int mf = 0; mf < 4; mf++)
#pragma unroll
        for (int nf = 0; nf < 4; nf++)
#pragma unroll
            for (int hh2 = 0; hh2 < 2; hh2++) {
                float hid  = c[mf][nf][hh2 * 2];
                float gate = c[mf][nf][hh2 * 2 + 1];
                float z  = sigm(gate);
                float gg = (hid >= 0.0f) ? (hid + 0.5f) : sigm(hid);
                int r = rloc + mf * 16 + hh2 * 8;
                int j = jloc + nf * 4;
                sa [r * 68 + j] = 1.0f - z;
                sbb[r * 68 + j] = z * gg;
            }
    __syncthreads();
#pragma unroll
    for (int it = 0; it < 8; it++) {
        int idx = tid + it * 256;          // 2048 float4 segments
        int row = idx >> 4, seg = idx & 15;
        size_t off = ((size_t)b * SS + m0 + row) * DD + (n0 >> 1) + seg * 4;
        float4 va = *(float4*)&sa [row * 68 + seg * 4];
        float4 vb = *(float4*)&sbb[row * 68 + seg * 4];
        *(float4*)&g_a[off] = va;
        *(float4*)&g_b[off] = vb;
    }
}

// ---------------- GEMM2: out = h @ Wo^T + inputs ------------------------------------
__global__ void __launch_bounds__(256, 1) k_gemm2(const float* __restrict__ inputs,
                                                  float* __restrict__ out) {
    extern __shared__ __align__(128) char smraw[];
    uint32_t sb = cvta_smem(smraw);
    int tid = threadIdx.x;
    int b = blockIdx.z, m0 = blockIdx.y * 128, n0 = blockIdx.x * 128;

    const __half* Ah = g_hh + ((size_t)b * SS + m0) * DD;
    const __half* Al = g_hl + ((size_t)b * SS + m0) * DD;
    const __half* Bh = g_wo + ((size_t)b * DD + n0) * DD;

    float c[4][4][4];
#pragma unroll
    for (int i = 0; i < 4; i++)
#pragma unroll
        for (int j = 0; j < 4; j++)
#pragma unroll
            for (int k = 0; k < 4; k++) c[i][j][k] = 0.0f;

    gemm_mainloop(c, sb, Ah, Al, Bh, tid);

    int lane = tid & 31, wid = tid >> 5;
    int wm = wid >> 2, wn = wid & 3;
    int rbase = m0 + wm * 64 + (lane >> 2);
    int cbase = n0 + wn * 32 + (lane & 3) * 2;
#pragma unroll
    for (int mf = 0; mf < 4; mf++)
#pragma unroll
        for (int nf = 0; nf < 4; nf++)
#pragma unroll
            for (int hh2 = 0; hh2 < 2; hh2++) {
                int row = rbase + mf * 16 + hh2 * 8;
                int col = cbase + nf * 8;
                size_t off = ((size_t)b * SS + row) * DD + col;
                float2 iv = *(const float2*)&inputs[off];
                float2 ov;
                ov.x = c[mf][nf][hh2 * 2]     + iv.x;
                ov.y = c[mf][nf][hh2 * 2 + 1] + iv.y;
                *(float2*)&out[off] = ov;
            }
}

// ---------------- scan ----------------------------------------------------------------
__global__ void k_scanA(const float* __restrict__ state) {
    int idx = blockIdx.x * 256 + threadIdx.x;
    int d = idx & (DD - 1);
    int c = (idx >> 10) & (NCH - 1);
    int b = idx >> 16;
    size_t base = (size_t)(b * SS + c * CL) * DD + d;
    float A = 1.0f, Bc = 0.0f;
#pragma unroll 8
    for (int s = 0; s < CL; s++) {
        float as = g_a[base + (size_t)s * DD];
        float bs = g_b[base + (size_t)s * DD];
        if (c == 0 && s == 0) bs += as * state[b * DD + d];
        Bc = fmaf(as, Bc, bs);
        A *= as;
    }
    g_cA[idx] = A;
    g_cB[idx] = Bc;
}

__global__ void k_scanB() {
    int idx = blockIdx.x * 256 + threadIdx.x;
    int d = idx & (DD - 1);
    int b = idx >> 10;
    float h = 0.0f;
    for (int c = 0; c < NCH; c++) {
        int off = (b * NCH + c) * DD + d;
        float A = g_cA[off], Bc = g_cB[off];
        g_cB[off] = h;
        h = fmaf(A, h, Bc);
    }
}

__global__ void k_scanC(const float* __restrict__ state, float* out, int out_size) {
    int idx = blockIdx.x * 256 + threadIdx.x;
    int d = idx & (DD - 1);
    int c = (idx >> 10) & (NCH - 1);
    int b = idx >> 16;
    size_t base = (size_t)(b * SS + c * CL) * DD + d;
    float h = g_cB[idx];
#pragma unroll 8
    for (int s = 0; s < CL; s++) {
        float as = g_a[base + (size_t)s * DD];
        float bs = g_b[base + (size_t)s * DD];
        if (c == 0 && s == 0) bs += as * state[b * DD + d];
        h = fmaf(as, h, bs);
        __half hi = __float2half_rn(h);
        g_hh[base + (size_t)s * DD] = hi;
        g_hl[base + (size_t)s * DD] = __float2half_rn(h - __half2float(hi));
    }
    if (c == NCH - 1 && out_size >= BB*SS*DD + BB*DD)
        out[BB*SS*DD + b * DD + d] = h;
}

// ---------------- launch ------------------------------------------------------------
extern "C" void kernel_launch(void* const* d_in, const int* in_sizes, int n_in,
                              void* d_out, int out_size) {
    const float* inputs = (const float*)d_in[0];
    const float* state  = (const float*)d_in[1];
    const float* normw  = (const float*)d_in[2];
    const float* rw     = (const float*)d_in[3];
    const float* rb     = (const float*)d_in[4];
    const float* wgh    = (const float*)d_in[5];
    const float* wout   = (const float*)d_in[6];
    float* out = (float*)d_out;

    cudaFuncSetAttribute(k_gemm1, cudaFuncAttributeMaxDynamicSharedMemorySize, SMEM_BYTES);
    cudaFuncSetAttribute(k_gemm2, cudaFuncAttributeMaxDynamicSharedMemorySize, SMEM_BYTES);

    k_init   <<<32, 256>>>(out, out_size);
    k_rmsnorm<<<dim3(SS / 64, BB), 256>>>(inputs, normw);
    k_router <<<BB, 128>>>(rw, rb);
    k_mixgT  <<<dim3(1024, 2, BB), 256>>>(wgh);
    k_mixoT  <<<dim3(1024, 1, BB), 256>>>(wout);
    k_gemm1  <<<dim3(DD2 / 128, SS / 128, BB), 256, SMEM_BYTES>>>();
    k_scanA  <<<(BB * NCH * DD) / 256, 256>>>(state);
    k_scanB  <<<(BB * DD) / 256, 256>>>();
    k_scanC  <<<(BB * NCH * DD) / 256, 256>>>(state, out, out_size);
    k_gemm2  <<<dim3(DD / 128, SS / 128, BB), 256, SMEM_BYTES>>>(inputs, out);
}

// round 5
// speedup vs baseline: 3.8891x; 1.4070x over previous
#include <cuda_runtime.h>
#include <cuda_fp16.h>
#include <cstdint>
#include <math.h>

#define BB   8
#define SS   4096
#define DD   1024
#define DD2  2048
#define CL   64
#define NCH  64
#define EPSV 1e-5f

// ---------------- scratch (device globals) -----------------------------------
__device__ __half g_xh[BB*SS*DD];                   // rmsnorm x fp16
__device__ __half g_wg[BB*DD2*DD];                  // mixed Wg^T (interleaved n) fp16
__device__ __half g_wo[BB*DD*DD];                   // mixed Wo^T fp16
__device__ __half g_hh[BB*SS*DD];                   // scan h fp16
__device__ float g_a[BB*SS*DD], g_b[BB*SS*DD];
__device__ float g_colsum[BB*DD];
__device__ float g_probs [BB*3];
__device__ float g_cA[BB*NCH*DD], g_cB[BB*NCH*DD];

__device__ __forceinline__ float sigm(float x) { return 1.0f / (1.0f + __expf(-x)); }

__device__ __forceinline__ uint32_t cvta_smem(const void* p) {
    uint32_t a;
    asm("{ .reg .u64 t; cvta.to.shared.u64 t, %1; cvt.u32.u64 %0, t; }" : "=r"(a) : "l"(p));
    return a;
}

// ---------------- portable tensor-core primitives ------------------------------
__device__ __forceinline__ void mma16816(float* c, const uint32_t* a, const uint32_t* b) {
    asm volatile(
        "mma.sync.aligned.m16n8k16.row.col.f32.f16.f16.f32 "
        "{%0,%1,%2,%3},{%4,%5,%6,%7},{%8,%9},{%0,%1,%2,%3};"
        : "+f"(c[0]), "+f"(c[1]), "+f"(c[2]), "+f"(c[3])
        : "r"(a[0]), "r"(a[1]), "r"(a[2]), "r"(a[3]), "r"(b[0]), "r"(b[1]));
}
__device__ __forceinline__ void ldm4(uint32_t* r, uint32_t a) {
    asm volatile("ldmatrix.sync.aligned.m8n8.x4.shared.b16 {%0,%1,%2,%3}, [%4];"
        : "=r"(r[0]), "=r"(r[1]), "=r"(r[2]), "=r"(r[3]) : "r"(a));
}
#define CPA(s, g) asm volatile("cp.async.cg.shared.global [%0], [%1], 16;" :: "r"(s), "l"(g))
#define CP_COMMIT() asm volatile("cp.async.commit_group;")
#define CP_WAIT2()  asm volatile("cp.async.wait_group 2;")
#define CP_WAIT1()  asm volatile("cp.async.wait_group 1;")
#define CP_WAIT0()  asm volatile("cp.async.wait_group 0;")

// smem stage: A 128x80 | B 128x80  (BK=32 fp16 = 64B + 16B pad); 4 stages
#define MAT_BYTES  10240
#define STAGE_B    20480
#define SMEM_BYTES 81920          // 4 stages; also covers GEMM1 epilogue staging (69632B)

__device__ __forceinline__ void load_mat(uint32_t sdst, const __half* g, int tid) {
#pragma unroll
    for (int it = 0; it < 2; it++) {
        int idx = tid + it * 256;
        int r = idx >> 2, cc = idx & 3;
        CPA(sdst + r * 80 + cc * 16, g + (size_t)r * DD + cc * 8);
    }
}
__device__ __forceinline__ void load_stage(uint32_t sbuf,
    const __half* A, const __half* B, int k0, int tid) {
    load_mat(sbuf,             A + k0, tid);
    load_mat(sbuf + MAT_BYTES, B + k0, tid);
}

// 128x128 tile, 8 warps (2M x 4N), warp tile 64x32; single-term fp16, 4-stage pipe.
__device__ __forceinline__ void gemm_mainloop(
    float c[4][4][4], uint32_t sb,
    const __half* A, const __half* B, int tid) {

    int lane = tid & 31, wid = tid >> 5;
    int wm = wid >> 2, wn = wid & 3;
    uint32_t aoff = (uint32_t)(wm * 64 + (lane & 15)) * 80 + (lane >> 4) * 16;
    uint32_t boff = (uint32_t)(wn * 32 + (lane & 7) + ((lane >> 4) << 3)) * 80
                  + ((lane >> 3) & 1) * 16;

    load_stage(sb,               A, B, 0,  tid); CP_COMMIT();
    load_stage(sb + STAGE_B,     A, B, 32, tid); CP_COMMIT();
    load_stage(sb + 2 * STAGE_B, A, B, 64, tid); CP_COMMIT();

#pragma unroll 1
    for (int s = 0; s < 32; s++) {
        if (s < 30) CP_WAIT2();
        else if (s == 30) CP_WAIT1();
        else CP_WAIT0();
        __syncthreads();
        if (s < 29) {
            load_stage(sb + ((s + 3) & 3) * STAGE_B, A, B, (s + 3) * 32, tid);
            CP_COMMIT();
        }
        uint32_t base = sb + (s & 3) * STAGE_B;
#pragma unroll
        for (int ks = 0; ks < 2; ks++) {
            uint32_t ah[4][4], bh[2][4];
#pragma unroll
            for (int mf = 0; mf < 4; mf++)
                ldm4(ah[mf], base + aoff + mf * (16 * 80) + ks * 32);
#pragma unroll
            for (int ng = 0; ng < 2; ng++)
                ldm4(bh[ng], base + MAT_BYTES + boff + ng * (16 * 80) + ks * 32);
#pragma unroll
            for (int mf = 0; mf < 4; mf++)
#pragma unroll
                for (int nf = 0; nf < 4; nf++)
                    mma16816(c[mf][nf], ah[mf], &bh[nf >> 1][(nf & 1) * 2]);
        }
    }
    __syncthreads();
}

// ---------------- init ----------------------------------------------------------
__global__ void k_init(float* out, int out_size) {
    int idx = blockIdx.x * 256 + threadIdx.x;
    if (idx < BB * DD) g_colsum[idx] = 0.0f;
    if (idx == 0 && out_size >= BB*SS*DD + BB*DD + 1)
        out[BB*SS*DD + BB*DD] = 0.0f;
}

// ---------------- rmsnorm -> fp16 + colsum ---------------------------------------
__global__ void __launch_bounds__(256) k_rmsnorm(const float* __restrict__ inp,
                                                 const float* __restrict__ normw) {
    int b = blockIdx.y, t = threadIdx.x, warp = t >> 5, lane = t & 31;
    __shared__ float sw[DD];
    __shared__ float scs[DD];
    for (int i = t; i < DD; i += 256) { sw[i] = normw[i]; scs[i] = 0.0f; }
    __syncthreads();
    float csum[32];
#pragma unroll
    for (int k = 0; k < 32; k++) csum[k] = 0.0f;
    int s_base = blockIdx.x * 64;
#pragma unroll 1
    for (int r = 0; r < 8; r++) {
        int s = s_base + warp + r * 8;
        const float* row = inp + (size_t)(b * SS + s) * DD;
        float v[32], ss = 0.0f;
#pragma unroll
        for (int k = 0; k < 32; k++) { v[k] = row[lane + 32 * k]; ss += v[k] * v[k]; }
#pragma unroll
        for (int o = 16; o > 0; o >>= 1) ss += __shfl_xor_sync(0xffffffffu, ss, o);
        float inv = rsqrtf(ss * (1.0f / DD) + EPSV);
        size_t ro = (size_t)(b * SS + s) * DD;
#pragma unroll
        for (int k = 0; k < 32; k++) {
            float xv = v[k] * inv * sw[lane + 32 * k];
            g_xh[ro + lane + 32 * k] = __float2half_rn(xv);
            csum[k] += xv;
        }
    }
#pragma unroll
    for (int k = 0; k < 32; k++) atomicAdd(&scs[lane + 32 * k], csum[k]);
    __syncthreads();
    for (int i = t; i < DD; i += 256) atomicAdd(&g_colsum[b * DD + i], scs[i]);
}

// ---------------- router ----------------------------------------------------------
__global__ void k_router(const float* __restrict__ rw, const float* __restrict__ rb) {
    int b = blockIdx.x, t = threadIdx.x;
    float p0 = 0, p1 = 0, p2 = 0;
    for (int d = t; d < DD; d += 128) {
        float cs = g_colsum[b * DD + d] * (1.0f / SS);
        p0 += cs * rw[d * 3 + 0];
        p1 += cs * rw[d * 3 + 1];
        p2 += cs * rw[d * 3 + 2];
    }
    __shared__ float sm[3][128];
    sm[0][t] = p0; sm[1][t] = p1; sm[2][t] = p2;
    __syncthreads();
    for (int o = 64; o > 0; o >>= 1) {
        if (t < o) { sm[0][t] += sm[0][t+o]; sm[1][t] += sm[1][t+o]; sm[2][t] += sm[2][t+o]; }
        __syncthreads();
    }
    if (t == 0) {
        float l0 = sm[0][0] + rb[0], l1 = sm[1][0] + rb[1], l2 = sm[2][0] + rb[2];
        float m = fmaxf(l0, fmaxf(l1, l2));
        float e0 = __expf(l0-m), e1 = __expf(l1-m), e2 = __expf(l2-m);
        float inv = 1.0f / (e0 + e1 + e2);
        g_probs[b*3+0] = e0*inv; g_probs[b*3+1] = e1*inv; g_probs[b*3+2] = e2*inv;
    }
}

// ---------------- mix + transpose Wg (interleaved n = 2j+which) -> fp16 ----------
__global__ void __launch_bounds__(256) k_mixgT(const float* __restrict__ wgh) {
    int b = blockIdx.z, which = blockIdx.y;
    int jt = blockIdx.x & 31, kt2 = blockIdx.x >> 5;
    int j0 = jt * 32, k0 = kt2 * 32;
    float p0 = g_probs[b*3+0], p1 = g_probs[b*3+1], p2 = g_probs[b*3+2];
    __shared__ float s[32][33];
    int c = threadIdx.x & 31, r = threadIdx.x >> 5;
#pragma unroll
    for (int rr = 0; rr < 4; rr++) {
        int k = k0 + r + 8 * rr;
        size_t o0 = (size_t)k * DD2 + (size_t)which * DD + j0 + c;
        s[r + 8*rr][c] = p0 * wgh[o0] + p1 * wgh[o0 + (size_t)DD*DD2] + p2 * wgh[o0 + (size_t)2*DD*DD2];
    }
    __syncthreads();
#pragma unroll
    for (int rr = 0; rr < 4; rr++) {
        int jl = r + 8 * rr, kl = c;
        size_t off = ((size_t)b * DD2 + 2*(j0+jl) + which) * DD + k0 + kl;
        g_wg[off] = __float2half_rn(s[kl][jl]);
    }
}

// ---------------- mix + transpose Wo -> fp16 --------------------------------------
__global__ void __launch_bounds__(256) k_mixoT(const float* __restrict__ wout) {
    int b = blockIdx.z;
    int jt = blockIdx.x & 31, kt2 = blockIdx.x >> 5;
    int j0 = jt * 32, k0 = kt2 * 32;
    float p0 = g_probs[b*3+0], p1 = g_probs[b*3+1], p2 = g_probs[b*3+2];
    __shared__ float s[32][33];
    int c = threadIdx.x & 31, r = threadIdx.x >> 5;
#pragma unroll
    for (int rr = 0; rr < 4; rr++) {
        int k = k0 + r + 8 * rr;
        size_t o0 = (size_t)k * DD + j0 + c;
        s[r + 8*rr][c] = p0 * wout[o0] + p1 * wout[o0 + (size_t)DD*DD] + p2 * wout[o0 + (size_t)2*DD*DD];
    }
    __syncthreads();
#pragma unroll
    for (int rr = 0; rr < 4; rr++) {
        int jl = r + 8 * rr, kl = c;
        size_t off = ((size_t)b * DD + j0 + jl) * DD + k0 + kl;
        g_wo[off] = __float2half_rn(s[kl][jl]);
    }
}

// ---------------- GEMM1: hg = x @ Wg^T, epilogue -> a,b (smem-staged) -------------
__global__ void __launch_bounds__(256, 1) k_gemm1() {
    extern __shared__ __align__(128) char smraw[];
    uint32_t sb = cvta_smem(smraw);
    int tid = threadIdx.x;
    int b = blockIdx.z, m0 = blockIdx.y * 128, n0 = blockIdx.x * 128;

    const __half* A = g_xh + ((size_t)b * SS  + m0) * DD;
    const __half* B = g_wg + ((size_t)b * DD2 + n0) * DD;

    float c[4][4][4];
#pragma unroll
    for (int i = 0; i < 4; i++)
#pragma unroll
        for (int j = 0; j < 4; j++)
#pragma unroll
            for (int k = 0; k < 4; k++) c[i][j][k] = 0.0f;

    gemm_mainloop(c, sb, A, B, tid);

    // stage a,b into padded smem (pitch 68 floats), then coalesced write
    float* sa = (float*)smraw;            // 128 x 68 floats
    float* sbb = sa + 128 * 68;
    int lane = tid & 31, wid = tid >> 5;
    int wm = wid >> 2, wn = wid & 3;
    int rloc = wm * 64 + (lane >> 2);
    int jloc = wn * 16 + (lane & 3);
#pragma unroll
    for (int mf = 0; mf < 4; mf++)
#pragma unroll
        for (int nf = 0; nf < 4; nf++)
#pragma unroll
            for (int hh2 = 0; hh2 < 2; hh2++) {
                float hid  = c[mf][nf][hh2 * 2];
                float gate = c[mf][nf][hh2 * 2 + 1];
                float z  = sigm(gate);
                float gg = (hid >= 0.0f) ? (hid + 0.5f) : sigm(hid);
                int r = rloc + mf * 16 + hh2 * 8;
                int j = jloc + nf * 4;
                sa [r * 68 + j] = 1.0f - z;
                sbb[r * 68 + j] = z * gg;
            }
    __syncthreads();
#pragma unroll
    for (int it = 0; it < 8; it++) {
        int idx = tid + it * 256;
        int row = idx >> 4, seg = idx & 15;
        size_t off = ((size_t)b * SS + m0 + row) * DD + (n0 >> 1) + seg * 4;
        *(float4*)&g_a[off] = *(float4*)&sa [row * 68 + seg * 4];
        *(float4*)&g_b[off] = *(float4*)&sbb[row * 68 + seg * 4];
    }
}

// ---------------- GEMM2: out = h @ Wo^T + inputs ------------------------------------
__global__ void __launch_bounds__(256, 1) k_gemm2(const float* __restrict__ inputs,
                                                  float* __restrict__ out) {
    extern __shared__ __align__(128) char smraw[];
    uint32_t sb = cvta_smem(smraw);
    int tid = threadIdx.x;
    int b = blockIdx.z, m0 = blockIdx.y * 128, n0 = blockIdx.x * 128;

    const __half* A = g_hh + ((size_t)b * SS + m0) * DD;
    const __half* B = g_wo + ((size_t)b * DD + n0) * DD;

    float c[4][4][4];
#pragma unroll
    for (int i = 0; i < 4; i++)
#pragma unroll
        for (int j = 0; j < 4; j++)
#pragma unroll
            for (int k = 0; k < 4; k++) c[i][j][k] = 0.0f;

    gemm_mainloop(c, sb, A, B, tid);

    int lane = tid & 31, wid = tid >> 5;
    int wm = wid >> 2, wn = wid & 3;
    int rbase = m0 + wm * 64 + (lane >> 2);
    int cbase = n0 + wn * 32 + (lane & 3) * 2;
#pragma unroll
    for (int mf = 0; mf < 4; mf++)
#pragma unroll
        for (int nf = 0; nf < 4; nf++)
#pragma unroll
            for (int hh2 = 0; hh2 < 2; hh2++) {
                int row = rbase + mf * 16 + hh2 * 8;
                int col = cbase + nf * 8;
                size_t off = ((size_t)b * SS + row) * DD + col;
                float2 iv = *(const float2*)&inputs[off];
                float2 ov;
                ov.x = c[mf][nf][hh2 * 2]     + iv.x;
                ov.y = c[mf][nf][hh2 * 2 + 1] + iv.y;
                *(float2*)&out[off] = ov;
            }
}

// ---------------- scan ----------------------------------------------------------------
__global__ void k_scanA(const float* __restrict__ state) {
    int idx = blockIdx.x * 256 + threadIdx.x;
    int d = idx & (DD - 1);
    int c = (idx >> 10) & (NCH - 1);
    int b = idx >> 16;
    size_t base = (size_t)(b * SS + c * CL) * DD + d;
    float A = 1.0f, Bc = 0.0f;
#pragma unroll 8
    for (int s = 0; s < CL; s++) {
        float as = g_a[base + (size_t)s * DD];
        float bs = g_b[base + (size_t)s * DD];
        if (c == 0 && s == 0) bs += as * state[b * DD + d];
        Bc = fmaf(as, Bc, bs);
        A *= as;
    }
    g_cA[idx] = A;
    g_cB[idx] = Bc;
}

__global__ void k_scanB() {
    int idx = blockIdx.x * 256 + threadIdx.x;
    int d = idx & (DD - 1);
    int b = idx >> 10;
    float h = 0.0f;
    for (int c = 0; c < NCH; c++) {
        int off = (b * NCH + c) * DD + d;
        float A = g_cA[off], Bc = g_cB[off];
        g_cB[off] = h;
        h = fmaf(A, h, Bc);
    }
}

__global__ void k_scanC(const float* __restrict__ state, float* out, int out_size) {
    int idx = blockIdx.x * 256 + threadIdx.x;
    int d = idx & (DD - 1);
    int c = (idx >> 10) & (NCH - 1);
    int b = idx >> 16;
    size_t base = (size_t)(b * SS + c * CL) * DD + d;
    float h = g_cB[idx];
#pragma unroll 8
    for (int s = 0; s < CL; s++) {
        float as = g_a[base + (size_t)s * DD];
        float bs = g_b[base + (size_t)s * DD];
        if (c == 0 && s == 0) bs += as * state[b * DD + d];
        h = fmaf(as, h, bs);
        g_hh[base + (size_t)s * DD] = __float2half_rn(h);
    }
    if (c == NCH - 1 && out_size >= BB*SS*DD + BB*DD)
        out[BB*SS*DD + b * DD + d] = h;
}

// ---------------- launch ------------------------------------------------------------
extern "C" void kernel_launch(void* const* d_in, const int* in_sizes, int n_in,
                              void* d_out, int out_size) {
    const float* inputs = (const float*)d_in[0];
    const float* state  = (const float*)d_in[1];
    const float* normw  = (const float*)d_in[2];
    const float* rw     = (const float*)d_in[3];
    const float* rb     = (const float*)d_in[4];
    const float* wgh    = (const float*)d_in[5];
    const float* wout   = (const float*)d_in[6];
    float* out = (float*)d_out;

    cudaFuncSetAttribute(k_gemm1, cudaFuncAttributeMaxDynamicSharedMemorySize, SMEM_BYTES);
    cudaFuncSetAttribute(k_gemm2, cudaFuncAttributeMaxDynamicSharedMemorySize, SMEM_BYTES);

    k_init   <<<32, 256>>>(out, out_size);
    k_rmsnorm<<<dim3(SS / 64, BB), 256>>>(inputs, normw);
    k_router <<<BB, 128>>>(rw, rb);
    k_mixgT  <<<dim3(1024, 2, BB), 256>>>(wgh);
    k_mixoT  <<<dim3(1024, 1, BB), 256>>>(wout);
    k_gemm1  <<<dim3(DD2 / 128, SS / 128, BB), 256, SMEM_BYTES>>>();
    k_scanA  <<<(BB * NCH * DD) / 256, 256>>>(state);
    k_scanB  <<<(BB * DD) / 256, 256>>>();
    k_scanC  <<<(BB * NCH * DD) / 256, 256>>>(state, out, out_size);
    k_gemm2  <<<dim3(DD / 128, SS / 128, BB), 256, SMEM_BYTES>>>(inputs, out);
}

// round 6
// speedup vs baseline: 4.5887x; 1.1799x over previous
#include <cuda_runtime.h>
#include <cuda_fp16.h>
#include <cstdint>
#include <math.h>

#define BB   8
#define SS   4096
#define DD   1024
#define DD2  2048
#define CL   64
#define NCH  64
#define EPSV 1e-5f

// ---------------- scratch (device globals) -----------------------------------
__device__ __half g_xh[BB*SS*DD];                   // rmsnorm x fp16
__device__ __half g_wg[BB*DD2*DD];                  // mixed Wg^T (interleaved n) fp16
__device__ __half g_wo[BB*DD*DD];                   // mixed Wo^T fp16
__device__ __half g_hh[BB*SS*DD];                   // scan h fp16
__device__ __half2 g_ab[BB*SS*DD];                  // packed gates (a,b) fp16
__device__ float g_colsum[BB*DD];
__device__ float g_probs [BB*3];
__device__ float g_cA[BB*NCH*DD], g_cB[BB*NCH*DD];

__device__ __forceinline__ float sigm(float x) { return 1.0f / (1.0f + __expf(-x)); }

__device__ __forceinline__ uint32_t cvta_smem(const void* p) {
    uint32_t a;
    asm("{ .reg .u64 t; cvta.to.shared.u64 t, %1; cvt.u32.u64 %0, t; }" : "=r"(a) : "l"(p));
    return a;
}

// ---------------- portable tensor-core primitives ------------------------------
__device__ __forceinline__ void mma16816(float* c, const uint32_t* a, const uint32_t* b) {
    asm volatile(
        "mma.sync.aligned.m16n8k16.row.col.f32.f16.f16.f32 "
        "{%0,%1,%2,%3},{%4,%5,%6,%7},{%8,%9},{%0,%1,%2,%3};"
        : "+f"(c[0]), "+f"(c[1]), "+f"(c[2]), "+f"(c[3])
        : "r"(a[0]), "r"(a[1]), "r"(a[2]), "r"(a[3]), "r"(b[0]), "r"(b[1]));
}
__device__ __forceinline__ void ldm4(uint32_t* r, uint32_t a) {
    asm volatile("ldmatrix.sync.aligned.m8n8.x4.shared.b16 {%0,%1,%2,%3}, [%4];"
        : "=r"(r[0]), "=r"(r[1]), "=r"(r[2]), "=r"(r[3]) : "r"(a));
}
#define CPA(s, g) asm volatile("cp.async.cg.shared.global [%0], [%1], 16;" :: "r"(s), "l"(g))
#define CP_COMMIT() asm volatile("cp.async.commit_group;")
#define CP_WAIT2()  asm volatile("cp.async.wait_group 2;")
#define CP_WAIT1()  asm volatile("cp.async.wait_group 1;")
#define CP_WAIT0()  asm volatile("cp.async.wait_group 0;")

// smem stage: A 128x80 | B 256x80  (BK=32 fp16 = 64B + 16B pad); 4 stages
#define A_BYTES    10240
#define STAGE_B    30720
#define SMEM_BYTES 122880         // 4 stages; epilogue staging (67584B) fits too

template<int ROWS>
__device__ __forceinline__ void load_mat(uint32_t sdst, const __half* g, int tid) {
#pragma unroll
    for (int it = 0; it < ROWS * 4 / 256; it++) {
        int idx = tid + it * 256;
        int r = idx >> 2, cc = idx & 3;
        CPA(sdst + r * 80 + cc * 16, g + (size_t)r * DD + cc * 8);
    }
}
__device__ __forceinline__ void load_stage(uint32_t sbuf,
    const __half* A, const __half* B, int k0, int tid) {
    load_mat<128>(sbuf,           A + k0, tid);
    load_mat<256>(sbuf + A_BYTES, B + k0, tid);
}

// 128x256 tile, 8 warps (2M x 4N), warp tile 64x64; fp16, 4-stage pipe.
__device__ __forceinline__ void gemm_mainloop(
    float c[4][8][4], uint32_t sb,
    const __half* A, const __half* B, int tid) {

    int lane = tid & 31, wid = tid >> 5;
    int wm = wid >> 2, wn = wid & 3;
    uint32_t aoff = (uint32_t)(wm * 64 + (lane & 15)) * 80 + (lane >> 4) * 16;
    uint32_t boff = (uint32_t)(wn * 64 + (lane & 7) + ((lane >> 4) << 3)) * 80
                  + ((lane >> 3) & 1) * 16;

    load_stage(sb,               A, B, 0,  tid); CP_COMMIT();
    load_stage(sb + STAGE_B,     A, B, 32, tid); CP_COMMIT();
    load_stage(sb + 2 * STAGE_B, A, B, 64, tid); CP_COMMIT();

#pragma unroll 1
    for (int s = 0; s < 32; s++) {
        if (s < 30) CP_WAIT2();
        else if (s == 30) CP_WAIT1();
        else CP_WAIT0();
        __syncthreads();
        if (s < 29) {
            load_stage(sb + ((s + 3) & 3) * STAGE_B, A, B, (s + 3) * 32, tid);
            CP_COMMIT();
        }
        uint32_t base = sb + (s & 3) * STAGE_B;
#pragma unroll
        for (int ks = 0; ks < 2; ks++) {
            uint32_t ah[4][4], bh[4][4];
#pragma unroll
            for (int mf = 0; mf < 4; mf++)
                ldm4(ah[mf], base + aoff + mf * (16 * 80) + ks * 32);
#pragma unroll
            for (int ng = 0; ng < 4; ng++)
                ldm4(bh[ng], base + A_BYTES + boff + ng * (16 * 80) + ks * 32);
#pragma unroll
            for (int mf = 0; mf < 4; mf++)
#pragma unroll
                for (int nf = 0; nf < 8; nf++)
                    mma16816(c[mf][nf], ah[mf], &bh[nf >> 1][(nf & 1) * 2]);
        }
    }
    __syncthreads();
}

// ---------------- init ----------------------------------------------------------
__global__ void k_init(float* out, int out_size) {
    int idx = blockIdx.x * 256 + threadIdx.x;
    if (idx < BB * DD) g_colsum[idx] = 0.0f;
    if (idx == 0 && out_size >= BB*SS*DD + BB*DD + 1)
        out[BB*SS*DD + BB*DD] = 0.0f;
}

// ---------------- rmsnorm -> fp16 + colsum ---------------------------------------
__global__ void __launch_bounds__(256) k_rmsnorm(const float* __restrict__ inp,
                                                 const float* __restrict__ normw) {
    int b = blockIdx.y, t = threadIdx.x, warp = t >> 5, lane = t & 31;
    __shared__ float sw[DD];
    __shared__ float scs[DD];
    for (int i = t; i < DD; i += 256) { sw[i] = normw[i]; scs[i] = 0.0f; }
    __syncthreads();
    float csum[32];
#pragma unroll
    for (int k = 0; k < 32; k++) csum[k] = 0.0f;
    int s_base = blockIdx.x * 64;
#pragma unroll 1
    for (int r = 0; r < 8; r++) {
        int s = s_base + warp + r * 8;
        const float* row = inp + (size_t)(b * SS + s) * DD;
        float v[32], ss = 0.0f;
#pragma unroll
        for (int k = 0; k < 32; k++) { v[k] = row[lane + 32 * k]; ss += v[k] * v[k]; }
#pragma unroll
        for (int o = 16; o > 0; o >>= 1) ss += __shfl_xor_sync(0xffffffffu, ss, o);
        float inv = rsqrtf(ss * (1.0f / DD) + EPSV);
        size_t ro = (size_t)(b * SS + s) * DD;
#pragma unroll
        for (int k = 0; k < 32; k++) {
            float xv = v[k] * inv * sw[lane + 32 * k];
            g_xh[ro + lane + 32 * k] = __float2half_rn(xv);
            csum[k] += xv;
        }
    }
#pragma unroll
    for (int k = 0; k < 32; k++) atomicAdd(&scs[lane + 32 * k], csum[k]);
    __syncthreads();
    for (int i = t; i < DD; i += 256) atomicAdd(&g_colsum[b * DD + i], scs[i]);
}

// ---------------- router ----------------------------------------------------------
__global__ void k_router(const float* __restrict__ rw, const float* __restrict__ rb) {
    int b = blockIdx.x, t = threadIdx.x;
    float p0 = 0, p1 = 0, p2 = 0;
    for (int d = t; d < DD; d += 128) {
        float cs = g_colsum[b * DD + d] * (1.0f / SS);
        p0 += cs * rw[d * 3 + 0];
        p1 += cs * rw[d * 3 + 1];
        p2 += cs * rw[d * 3 + 2];
    }
    __shared__ float sm[3][128];
    sm[0][t] = p0; sm[1][t] = p1; sm[2][t] = p2;
    __syncthreads();
    for (int o = 64; o > 0; o >>= 1) {
        if (t < o) { sm[0][t] += sm[0][t+o]; sm[1][t] += sm[1][t+o]; sm[2][t] += sm[2][t+o]; }
        __syncthreads();
    }
    if (t == 0) {
        float l0 = sm[0][0] + rb[0], l1 = sm[1][0] + rb[1], l2 = sm[2][0] + rb[2];
        float m = fmaxf(l0, fmaxf(l1, l2));
        float e0 = __expf(l0-m), e1 = __expf(l1-m), e2 = __expf(l2-m);
        float inv = 1.0f / (e0 + e1 + e2);
        g_probs[b*3+0] = e0*inv; g_probs[b*3+1] = e1*inv; g_probs[b*3+2] = e2*inv;
    }
}

// ---------------- mix + transpose Wg (interleaved n = 2j+which) -> fp16 ----------
__global__ void __launch_bounds__(256) k_mixgT(const float* __restrict__ wgh) {
    int b = blockIdx.z, which = blockIdx.y;
    int jt = blockIdx.x & 31, kt2 = blockIdx.x >> 5;
    int j0 = jt * 32, k0 = kt2 * 32;
    float p0 = g_probs[b*3+0], p1 = g_probs[b*3+1], p2 = g_probs[b*3+2];
    __shared__ float s[32][33];
    int c = threadIdx.x & 31, r = threadIdx.x >> 5;
#pragma unroll
    for (int rr = 0; rr < 4; rr++) {
        int k = k0 + r + 8 * rr;
        size_t o0 = (size_t)k * DD2 + (size_t)which * DD + j0 + c;
        s[r + 8*rr][c] = p0 * wgh[o0] + p1 * wgh[o0 + (size_t)DD*DD2] + p2 * wgh[o0 + (size_t)2*DD*DD2];
    }
    __syncthreads();
#pragma unroll
    for (int rr = 0; rr < 4; rr++) {
        int jl = r + 8 * rr, kl = c;
        size_t off = ((size_t)b * DD2 + 2*(j0+jl) + which) * DD + k0 + kl;
        g_wg[off] = __float2half_rn(s[kl][jl]);
    }
}

// ---------------- mix + transpose Wo -> fp16 --------------------------------------
__global__ void __launch_bounds__(256) k_mixoT(const float* __restrict__ wout) {
    int b = blockIdx.z;
    int jt = blockIdx.x & 31, kt2 = blockIdx.x >> 5;
    int j0 = jt * 32, k0 = kt2 * 32;
    float p0 = g_probs[b*3+0], p1 = g_probs[b*3+1], p2 = g_probs[b*3+2];
    __shared__ float s[32][33];
    int c = threadIdx.x & 31, r = threadIdx.x >> 5;
#pragma unroll
    for (int rr = 0; rr < 4; rr++) {
        int k = k0 + r + 8 * rr;
        size_t o0 = (size_t)k * DD + j0 + c;
        s[r + 8*rr][c] = p0 * wout[o0] + p1 * wout[o0 + (size_t)DD*DD] + p2 * wout[o0 + (size_t)2*DD*DD];
    }
    __syncthreads();
#pragma unroll
    for (int rr = 0; rr < 4; rr++) {
        int jl = r + 8 * rr, kl = c;
        size_t off = ((size_t)b * DD + j0 + jl) * DD + k0 + kl;
        g_wo[off] = __float2half_rn(s[kl][jl]);
    }
}

// ---------------- GEMM1: hg = x @ Wg^T, epilogue -> packed (a,b) -------------------
__global__ void __launch_bounds__(256, 1) k_gemm1() {
    extern __shared__ __align__(128) char smraw[];
    uint32_t sb = cvta_smem(smraw);
    int tid = threadIdx.x;
    int b = blockIdx.z, m0 = blockIdx.y * 128, n0 = blockIdx.x * 256;

    const __half* A = g_xh + ((size_t)b * SS  + m0) * DD;
    const __half* B = g_wg + ((size_t)b * DD2 + n0) * DD;

    float c[4][8][4];
#pragma unroll
    for (int i = 0; i < 4; i++)
#pragma unroll
        for (int j = 0; j < 8; j++)
#pragma unroll
            for (int k = 0; k < 4; k++) c[i][j][k] = 0.0f;

    gemm_mainloop(c, sb, A, B, tid);

    // stage packed (a,b) half2 into smem (128 rows x 128 j, pitch 132), coalesced write
    uint32_t* sab = (uint32_t*)smraw;
    int lane = tid & 31, wid = tid >> 5;
    int wm = wid >> 2, wn = wid & 3;
    int rloc = wm * 64 + (lane >> 2);
    int jloc = wn * 32 + (lane & 3);
#pragma unroll
    for (int mf = 0; mf < 4; mf++)
#pragma unroll
        for (int nf = 0; nf < 8; nf++)
#pragma unroll
            for (int hh2 = 0; hh2 < 2; hh2++) {
                float hid  = c[mf][nf][hh2 * 2];
                float gate = c[mf][nf][hh2 * 2 + 1];
                float z  = sigm(gate);
                float gg = (hid >= 0.0f) ? (hid + 0.5f) : sigm(hid);
                int r = rloc + mf * 16 + hh2 * 8;
                int j = jloc + nf * 4;
                __half2 v = __floats2half2_rn(1.0f - z, z * gg);
                sab[r * 132 + j] = *(uint32_t*)&v;
            }
    __syncthreads();
#pragma unroll
    for (int it = 0; it < 16; it++) {
        int idx = tid + it * 256;         // 4096 uint4 = 128 rows x 32 segs
        int row = idx >> 5, seg = idx & 31;
        size_t off = ((size_t)b * SS + m0 + row) * DD + (n0 >> 1) + seg * 4;
        uint4 v = *(uint4*)&sab[row * 132 + seg * 4];
        *(uint4*)&g_ab[off] = v;
    }
}

// ---------------- GEMM2: out = h @ Wo^T + inputs ------------------------------------
__global__ void __launch_bounds__(256, 1) k_gemm2(const float* __restrict__ inputs,
                                                  float* __restrict__ out) {
    extern __shared__ __align__(128) char smraw[];
    uint32_t sb = cvta_smem(smraw);
    int tid = threadIdx.x;
    int b = blockIdx.z, m0 = blockIdx.y * 128, n0 = blockIdx.x * 256;

    const __half* A = g_hh + ((size_t)b * SS + m0) * DD;
    const __half* B = g_wo + ((size_t)b * DD + n0) * DD;

    float c[4][8][4];
#pragma unroll
    for (int i = 0; i < 4; i++)
#pragma unroll
        for (int j = 0; j < 8; j++)
#pragma unroll
            for (int k = 0; k < 4; k++) c[i][j][k] = 0.0f;

    gemm_mainloop(c, sb, A, B, tid);

    int lane = tid & 31, wid = tid >> 5;
    int wm = wid >> 2, wn = wid & 3;
    int rbase = m0 + wm * 64 + (lane >> 2);
    int cbase = n0 + wn * 64 + (lane & 3) * 2;
#pragma unroll
    for (int mf = 0; mf < 4; mf++)
#pragma unroll
        for (int nf = 0; nf < 8; nf++)
#pragma unroll
            for (int hh2 = 0; hh2 < 2; hh2++) {
                int row = rbase + mf * 16 + hh2 * 8;
                int col = cbase + nf * 8;
                size_t off = ((size_t)b * SS + row) * DD + col;
                float2 iv = *(const float2*)&inputs[off];
                float2 ov;
                ov.x = c[mf][nf][hh2 * 2]     + iv.x;
                ov.y = c[mf][nf][hh2 * 2 + 1] + iv.y;
                *(float2*)&out[off] = ov;
            }
}

// ---------------- scan ----------------------------------------------------------------
__global__ void k_scanA(const float* __restrict__ state) {
    int idx = blockIdx.x * 256 + threadIdx.x;
    int d = idx & (DD - 1);
    int c = (idx >> 10) & (NCH - 1);
    int b = idx >> 16;
    size_t base = (size_t)(b * SS + c * CL) * DD + d;
    float A = 1.0f, Bc = 0.0f;
#pragma unroll 8
    for (int s = 0; s < CL; s++) {
        __half2 ab = g_ab[base + (size_t)s * DD];
        float as = __low2float(ab);
        float bs = __high2float(ab);
        if (c == 0 && s == 0) bs += as * state[b * DD + d];
        Bc = fmaf(as, Bc, bs);
        A *= as;
    }
    g_cA[idx] = A;
    g_cB[idx] = Bc;
}

__global__ void k_scanB() {
    int idx = blockIdx.x * 256 + threadIdx.x;
    int d = idx & (DD - 1);
    int b = idx >> 10;
    float h = 0.0f;
    for (int c = 0; c < NCH; c++) {
        int off = (b * NCH + c) * DD + d;
        float A = g_cA[off], Bc = g_cB[off];
        g_cB[off] = h;
        h = fmaf(A, h, Bc);
    }
}

__global__ void k_scanC(const float* __restrict__ state, float* out, int out_size) {
    int idx = blockIdx.x * 256 + threadIdx.x;
    int d = idx & (DD - 1);
    int c = (idx >> 10) & (NCH - 1);
    int b = idx >> 16;
    size_t base = (size_t)(b * SS + c * CL) * DD + d;
    float h = g_cB[idx];
#pragma unroll 8
    for (int s = 0; s < CL; s++) {
        __half2 ab = g_ab[base + (size_t)s * DD];
        float as = __low2float(ab);
        float bs = __high2float(ab);
        if (c == 0 && s == 0) bs += as * state[b * DD + d];
        h = fmaf(as, h, bs);
        g_hh[base + (size_t)s * DD] = __float2half_rn(h);
    }
    if (c == NCH - 1 && out_size >= BB*SS*DD + BB*DD)
        out[BB*SS*DD + b * DD + d] = h;
}

// ---------------- launch ------------------------------------------------------------
extern "C" void kernel_launch(void* const* d_in, const int* in_sizes, int n_in,
                              void* d_out, int out_size) {
    const float* inputs = (const float*)d_in[0];
    const float* state  = (const float*)d_in[1];
    const float* normw  = (const float*)d_in[2];
    const float* rw     = (const float*)d_in[3];
    const float* rb     = (const float*)d_in[4];
    const float* wgh    = (const float*)d_in[5];
    const float* wout   = (const float*)d_in[6];
    float* out = (float*)d_out;

    cudaFuncSetAttribute(k_gemm1, cudaFuncAttributeMaxDynamicSharedMemorySize, SMEM_BYTES);
    cudaFuncSetAttribute(k_gemm2, cudaFuncAttributeMaxDynamicSharedMemorySize, SMEM_BYTES);

    k_init   <<<32, 256>>>(out, out_size);
    k_rmsnorm<<<dim3(SS / 64, BB), 256>>>(inputs, normw);
    k_router <<<BB, 128>>>(rw, rb);
    k_mixgT  <<<dim3(1024, 2, BB), 256>>>(wgh);
    k_mixoT  <<<dim3(1024, 1, BB), 256>>>(wout);
    k_gemm1  <<<dim3(DD2 / 256, SS / 128, BB), 256, SMEM_BYTES>>>();
    k_scanA  <<<(BB * NCH * DD) / 256, 256>>>(state);
    k_scanB  <<<(BB * DD) / 256, 256>>>();
    k_scanC  <<<(BB * NCH * DD) / 256, 256>>>(state, out, out_size);
    k_gemm2  <<<dim3(DD / 256, SS / 128, BB), 256, SMEM_BYTES>>>(inputs, out);
}

// round 7
// speedup vs baseline: 5.0765x; 1.1063x over previous
#include <cuda_runtime.h>
#include <cuda_fp16.h>
#include <cstdint>
#include <math.h>

#define BB   8
#define SS   4096
#define DD   1024
#define DD2  2048
#define CL   64
#define NCH  64
#define EPSV 1e-5f

// ---------------- scratch (device globals) -----------------------------------
__device__ __half g_xh[BB*SS*DD];                   // rmsnorm x fp16
__device__ __half g_wg[BB*DD2*DD];                  // mixed Wg^T (interleaved n) fp16
__device__ __half g_wo[BB*DD*DD];                   // mixed Wo^T fp16
__device__ __half g_hh[BB*SS*DD];                   // scan h fp16
__device__ __half2 g_ab[BB*SS*DD];                  // packed gates (a,b) fp16
__device__ float g_colsum[BB*DD];
__device__ float g_probs [BB*3];
__device__ float g_cA[BB*NCH*DD], g_cB[BB*NCH*DD];

__device__ __forceinline__ float sigm(float x) { return 1.0f / (1.0f + __expf(-x)); }

__device__ __forceinline__ uint32_t cvta_smem(const void* p) {
    uint32_t a;
    asm("{ .reg .u64 t; cvta.to.shared.u64 t, %1; cvt.u32.u64 %0, t; }" : "=r"(a) : "l"(p));
    return a;
}

// ---------------- portable tensor-core primitives ------------------------------
__device__ __forceinline__ void mma16816(float* c, const uint32_t* a, const uint32_t* b) {
    asm volatile(
        "mma.sync.aligned.m16n8k16.row.col.f32.f16.f16.f32 "
        "{%0,%1,%2,%3},{%4,%5,%6,%7},{%8,%9},{%0,%1,%2,%3};"
        : "+f"(c[0]), "+f"(c[1]), "+f"(c[2]), "+f"(c[3])
        : "r"(a[0]), "r"(a[1]), "r"(a[2]), "r"(a[3]), "r"(b[0]), "r"(b[1]));
}
__device__ __forceinline__ void ldm4(uint32_t* r, uint32_t a) {
    asm volatile("ldmatrix.sync.aligned.m8n8.x4.shared.b16 {%0,%1,%2,%3}, [%4];"
        : "=r"(r[0]), "=r"(r[1]), "=r"(r[2]), "=r"(r[3]) : "r"(a));
}
#define CPA(s, g) asm volatile("cp.async.cg.shared.global [%0], [%1], 16;" :: "r"(s), "l"(g))
#define CP_COMMIT() asm volatile("cp.async.commit_group;")
#define CP_WAIT2()  asm volatile("cp.async.wait_group 2;")
#define CP_WAIT1()  asm volatile("cp.async.wait_group 1;")
#define CP_WAIT0()  asm volatile("cp.async.wait_group 0;")

// smem stage (BK=64): A 128x(128+16) | B 256x(128+16); 4 stages
#define A_BYTES    18432
#define B_BYTES    36864
#define STAGE_B    55296
#define SMEM_BYTES 221184        // 4 stages; epilogue staging (67.6KB) aliases it

template<int ROWS>
__device__ __forceinline__ void load_mat(uint32_t sdst, const __half* g, int tid) {
#pragma unroll
    for (int it = 0; it < ROWS * 8 / 256; it++) {
        int idx = tid + it * 256;
        int r = idx >> 3, cc = idx & 7;
        CPA(sdst + r * 144 + cc * 16, g + (size_t)r * DD + cc * 8);
    }
}
__device__ __forceinline__ void load_stage(uint32_t sbuf,
    const __half* A, const __half* B, int k0, int tid) {
    load_mat<128>(sbuf,           A + k0, tid);
    load_mat<256>(sbuf + A_BYTES, B + k0, tid);
}

// 128x256 tile, 8 warps (2M x 4N), warp tile 64x64; fp16, BK=64, 4-stage pipe.
__device__ __forceinline__ void gemm_mainloop(
    float c[4][8][4], uint32_t sb,
    const __half* A, const __half* B, int tid) {

    int lane = tid & 31, wid = tid >> 5;
    int wm = wid >> 2, wn = wid & 3;
    uint32_t aoff = (uint32_t)(wm * 64 + (lane & 15)) * 144 + (lane >> 4) * 16;
    uint32_t boff = (uint32_t)(wn * 64 + (lane & 7) + ((lane >> 4) << 3)) * 144
                  + ((lane >> 3) & 1) * 16;

    load_stage(sb,               A, B, 0,   tid); CP_COMMIT();
    load_stage(sb + STAGE_B,     A, B, 64,  tid); CP_COMMIT();
    load_stage(sb + 2 * STAGE_B, A, B, 128, tid); CP_COMMIT();

#pragma unroll 1
    for (int s = 0; s < 16; s++) {
        if (s < 14) CP_WAIT2();
        else if (s == 14) CP_WAIT1();
        else CP_WAIT0();
        __syncthreads();
        if (s < 13) {
            load_stage(sb + ((s + 3) & 3) * STAGE_B, A, B, (s + 3) * 64, tid);
            CP_COMMIT();
        }
        uint32_t base = sb + (s & 3) * STAGE_B;
#pragma unroll
        for (int ks = 0; ks < 4; ks++) {
            uint32_t ah[4][4], bh[4][4];
#pragma unroll
            for (int mf = 0; mf < 4; mf++)
                ldm4(ah[mf], base + aoff + mf * (16 * 144) + ks * 32);
#pragma unroll
            for (int ng = 0; ng < 4; ng++)
                ldm4(bh[ng], base + A_BYTES + boff + ng * (16 * 144) + ks * 32);
#pragma unroll
            for (int mf = 0; mf < 4; mf++)
#pragma unroll
                for (int nf = 0; nf < 8; nf++)
                    mma16816(c[mf][nf], ah[mf], &bh[nf >> 1][(nf & 1) * 2]);
        }
    }
    __syncthreads();
}

// ---------------- init ----------------------------------------------------------
__global__ void k_init(float* out, int out_size) {
    int idx = blockIdx.x * 256 + threadIdx.x;
    if (idx < BB * DD) g_colsum[idx] = 0.0f;
    if (idx == 0 && out_size >= BB*SS*DD + BB*DD + 1)
        out[BB*SS*DD + BB*DD] = 0.0f;
}

// ---------------- rmsnorm -> fp16 + colsum ---------------------------------------
__global__ void __launch_bounds__(256) k_rmsnorm(const float* __restrict__ inp,
                                                 const float* __restrict__ normw) {
    int b = blockIdx.y, t = threadIdx.x, warp = t >> 5, lane = t & 31;
    __shared__ float sw[DD];
    __shared__ float scs[DD];
    for (int i = t; i < DD; i += 256) { sw[i] = normw[i]; scs[i] = 0.0f; }
    __syncthreads();
    float csum[32];
#pragma unroll
    for (int k = 0; k < 32; k++) csum[k] = 0.0f;
    int s_base = blockIdx.x * 64;
#pragma unroll 1
    for (int r = 0; r < 8; r++) {
        int s = s_base + warp + r * 8;
        const float* row = inp + (size_t)(b * SS + s) * DD;
        float v[32], ss = 0.0f;
#pragma unroll
        for (int k = 0; k < 32; k++) { v[k] = row[lane + 32 * k]; ss += v[k] * v[k]; }
#pragma unroll
        for (int o = 16; o > 0; o >>= 1) ss += __shfl_xor_sync(0xffffffffu, ss, o);
        float inv = rsqrtf(ss * (1.0f / DD) + EPSV);
        size_t ro = (size_t)(b * SS + s) * DD;
#pragma unroll
        for (int k = 0; k < 32; k++) {
            float xv = v[k] * inv * sw[lane + 32 * k];
            g_xh[ro + lane + 32 * k] = __float2half_rn(xv);
            csum[k] += xv;
        }
    }
#pragma unroll
    for (int k = 0; k < 32; k++) atomicAdd(&scs[lane + 32 * k], csum[k]);
    __syncthreads();
    for (int i = t; i < DD; i += 256) atomicAdd(&g_colsum[b * DD + i], scs[i]);
}

// ---------------- router ----------------------------------------------------------
__global__ void k_router(const float* __restrict__ rw, const float* __restrict__ rb) {
    int b = blockIdx.x, t = threadIdx.x;
    float p0 = 0, p1 = 0, p2 = 0;
    for (int d = t; d < DD; d += 128) {
        float cs = g_colsum[b * DD + d] * (1.0f / SS);
        p0 += cs * rw[d * 3 + 0];
        p1 += cs * rw[d * 3 + 1];
        p2 += cs * rw[d * 3 + 2];
    }
    __shared__ float sm[3][128];
    sm[0][t] = p0; sm[1][t] = p1; sm[2][t] = p2;
    __syncthreads();
    for (int o = 64; o > 0; o >>= 1) {
        if (t < o) { sm[0][t] += sm[0][t+o]; sm[1][t] += sm[1][t+o]; sm[2][t] += sm[2][t+o]; }
        __syncthreads();
    }
    if (t == 0) {
        float l0 = sm[0][0] + rb[0], l1 = sm[1][0] + rb[1], l2 = sm[2][0] + rb[2];
        float m = fmaxf(l0, fmaxf(l1, l2));
        float e0 = __expf(l0-m), e1 = __expf(l1-m), e2 = __expf(l2-m);
        float inv = 1.0f / (e0 + e1 + e2);
        g_probs[b*3+0] = e0*inv; g_probs[b*3+1] = e1*inv; g_probs[b*3+2] = e2*inv;
    }
}

// ---------------- mix + transpose Wg (interleaved n) -> fp16; b in fastest dim ---
__global__ void __launch_bounds__(256) k_mixgT(const float* __restrict__ wgh) {
    int b = blockIdx.x & 7;
    int tile = blockIdx.x >> 3;
    int which = blockIdx.y;
    int jt = tile & 31, kt2 = tile >> 5;
    int j0 = jt * 32, k0 = kt2 * 32;
    float p0 = g_probs[b*3+0], p1 = g_probs[b*3+1], p2 = g_probs[b*3+2];
    __shared__ float s[32][33];
    int c = threadIdx.x & 31, r = threadIdx.x >> 5;
#pragma unroll
    for (int rr = 0; rr < 4; rr++) {
        int k = k0 + r + 8 * rr;
        size_t o0 = (size_t)k * DD2 + (size_t)which * DD + j0 + c;
        s[r + 8*rr][c] = p0 * wgh[o0] + p1 * wgh[o0 + (size_t)DD*DD2] + p2 * wgh[o0 + (size_t)2*DD*DD2];
    }
    __syncthreads();
#pragma unroll
    for (int rr = 0; rr < 4; rr++) {
        int jl = r + 8 * rr, kl = c;
        size_t off = ((size_t)b * DD2 + 2*(j0+jl) + which) * DD + k0 + kl;
        g_wg[off] = __float2half_rn(s[kl][jl]);
    }
}

// ---------------- mix + transpose Wo -> fp16; b in fastest dim --------------------
__global__ void __launch_bounds__(256) k_mixoT(const float* __restrict__ wout) {
    int b = blockIdx.x & 7;
    int tile = blockIdx.x >> 3;
    int jt = tile & 31, kt2 = tile >> 5;
    int j0 = jt * 32, k0 = kt2 * 32;
    float p0 = g_probs[b*3+0], p1 = g_probs[b*3+1], p2 = g_probs[b*3+2];
    __shared__ float s[32][33];
    int c = threadIdx.x & 31, r = threadIdx.x >> 5;
#pragma unroll
    for (int rr = 0; rr < 4; rr++) {
        int k = k0 + r + 8 * rr;
        size_t o0 = (size_t)k * DD + j0 + c;
        s[r + 8*rr][c] = p0 * wout[o0] + p1 * wout[o0 + (size_t)DD*DD] + p2 * wout[o0 + (size_t)2*DD*DD];
    }
    __syncthreads();
#pragma unroll
    for (int rr = 0; rr < 4; rr++) {
        int jl = r + 8 * rr, kl = c;
        size_t off = ((size_t)b * DD + j0 + jl) * DD + k0 + kl;
        g_wo[off] = __float2half_rn(s[kl][jl]);
    }
}

// ---------------- GEMM1: hg = x @ Wg^T -> packed (a,b) + fused chunk-scan ---------
__global__ void __launch_bounds__(256, 1) k_gemm1(const float* __restrict__ state) {
    extern __shared__ __align__(128) char smraw[];
    uint32_t sb = cvta_smem(smraw);
    int tid = threadIdx.x;
    int b = blockIdx.z, m0 = blockIdx.y * 128, n0 = blockIdx.x * 256;

    const __half* A = g_xh + ((size_t)b * SS  + m0) * DD;
    const __half* B = g_wg + ((size_t)b * DD2 + n0) * DD;

    float c[4][8][4];
#pragma unroll
    for (int i = 0; i < 4; i++)
#pragma unroll
        for (int j = 0; j < 8; j++)
#pragma unroll
            for (int k = 0; k < 4; k++) c[i][j][k] = 0.0f;

    gemm_mainloop(c, sb, A, B, tid);

    // stage packed (a,b) half2 into smem (128 rows x 128 j, pitch 132)
    uint32_t* sab = (uint32_t*)smraw;
    int lane = tid & 31, wid = tid >> 5;
    int wm = wid >> 2, wn = wid & 3;
    int rloc = wm * 64 + (lane >> 2);
    int jloc = wn * 32 + (lane & 3);
#pragma unroll
    for (int mf = 0; mf < 4; mf++)
#pragma unroll
        for (int nf = 0; nf < 8; nf++)
#pragma unroll
            for (int hh2 = 0; hh2 < 2; hh2++) {
                float hid  = c[mf][nf][hh2 * 2];
                float gate = c[mf][nf][hh2 * 2 + 1];
                float z  = sigm(gate);
                float gg = (hid >= 0.0f) ? (hid + 0.5f) : sigm(hid);
                int r = rloc + mf * 16 + hh2 * 8;
                int j = jloc + nf * 4;
                __half2 v = __floats2half2_rn(1.0f - z, z * gg);
                sab[r * 132 + j] = *(uint32_t*)&v;
            }
    __syncthreads();

    // coalesced g_ab write
#pragma unroll
    for (int it = 0; it < 16; it++) {
        int idx = tid + it * 256;
        int row = idx >> 5, seg = idx & 31;
        size_t off = ((size_t)b * SS + m0 + row) * DD + (n0 >> 1) + seg * 4;
        uint4 v = *(uint4*)&sab[row * 132 + seg * 4];
        *(uint4*)&g_ab[off] = v;
    }

    // fused scanA: per-chunk (A,B) carries from smem (2 chunks x 128 d-pairs)
    {
        int chunk = tid >> 7, d = tid & 127;
        int cglob = (m0 >> 6) + chunk;
        int dglob = (n0 >> 1) + d;
        float Ac = 1.0f, Bc = 0.0f;
        const uint32_t* base = sab + chunk * 64 * 132 + d;
#pragma unroll 8
        for (int s = 0; s < CL; s++) {
            __half2 ab = *(const __half2*)&base[s * 132];
            float as = __low2float(ab);
            float bs = __high2float(ab);
            if (cglob == 0 && s == 0) bs += as * state[b * DD + dglob];
            Bc = fmaf(as, Bc, bs);
            Ac *= as;
        }
        int off = (b * NCH + cglob) * DD + dglob;
        g_cA[off] = Ac;
        g_cB[off] = Bc;
    }
}

// ---------------- GEMM2: out = h @ Wo^T + inputs ------------------------------------
__global__ void __launch_bounds__(256, 1) k_gemm2(const float* __restrict__ inputs,
                                                  float* __restrict__ out) {
    extern __shared__ __align__(128) char smraw[];
    uint32_t sb = cvta_smem(smraw);
    int tid = threadIdx.x;
    int b = blockIdx.z, m0 = blockIdx.y * 128, n0 = blockIdx.x * 256;

    const __half* A = g_hh + ((size_t)b * SS + m0) * DD;
    const __half* B = g_wo + ((size_t)b * DD + n0) * DD;

    float c[4][8][4];
#pragma unroll
    for (int i = 0; i < 4; i++)
#pragma unroll
        for (int j = 0; j < 8; j++)
#pragma unroll
            for (int k = 0; k < 4; k++) c[i][j][k] = 0.0f;

    gemm_mainloop(c, sb, A, B, tid);

    int lane = tid & 31, wid = tid >> 5;
    int wm = wid >> 2, wn = wid & 3;
    int rbase = m0 + wm * 64 + (lane >> 2);
    int cbase = n0 + wn * 64 + (lane & 3) * 2;
#pragma unroll
    for (int mf = 0; mf < 4; mf++)
#pragma unroll
        for (int nf = 0; nf < 8; nf++)
#pragma unroll
            for (int hh2 = 0; hh2 < 2; hh2++) {
                int row = rbase + mf * 16 + hh2 * 8;
                int col = cbase + nf * 8;
                size_t off = ((size_t)b * SS + row) * DD + col;
                float2 iv = *(const float2*)&inputs[off];
                float2 ov;
                ov.x = c[mf][nf][hh2 * 2]     + iv.x;
                ov.y = c[mf][nf][hh2 * 2 + 1] + iv.y;
                *(float2*)&out[off] = ov;
            }
}

// ---------------- scan (B: chunk carries; C: apply + h fp16) -----------------------
__global__ void k_scanB() {
    int idx = blockIdx.x * 256 + threadIdx.x;
    int d = idx & (DD - 1);
    int b = idx >> 10;
    float h = 0.0f;
    for (int c = 0; c < NCH; c++) {
        int off = (b * NCH + c) * DD + d;
        float A = g_cA[off], Bc = g_cB[off];
        g_cB[off] = h;
        h = fmaf(A, h, Bc);
    }
}

__global__ void k_scanC(const float* __restrict__ state, float* out, int out_size) {
    int idx = blockIdx.x * 256 + threadIdx.x;
    int d = idx & (DD - 1);
    int c = (idx >> 10) & (NCH - 1);
    int b = idx >> 16;
    size_t base = (size_t)(b * SS + c * CL) * DD + d;
    float h = g_cB[idx];
#pragma unroll 8
    for (int s = 0; s < CL; s++) {
        __half2 ab = g_ab[base + (size_t)s * DD];
        float as = __low2float(ab);
        float bs = __high2float(ab);
        if (c == 0 && s == 0) bs += as * state[b * DD + d];
        h = fmaf(as, h, bs);
        g_hh[base + (size_t)s * DD] = __float2half_rn(h);
    }
    if (c == NCH - 1 && out_size >= BB*SS*DD + BB*DD)
        out[BB*SS*DD + b * DD + d] = h;
}

// ---------------- launch ------------------------------------------------------------
extern "C" void kernel_launch(void* const* d_in, const int* in_sizes, int n_in,
                              void* d_out, int out_size) {
    const float* inputs = (const float*)d_in[0];
    const float* state  = (const float*)d_in[1];
    const float* normw  = (const float*)d_in[2];
    const float* rw     = (const float*)d_in[3];
    const float* rb     = (const float*)d_in[4];
    const float* wgh    = (const float*)d_in[5];
    const float* wout   = (const float*)d_in[6];
    float* out = (float*)d_out;

    cudaFuncSetAttribute(k_gemm1, cudaFuncAttributeMaxDynamicSharedMemorySize, SMEM_BYTES);
    cudaFuncSetAttribute(k_gemm2, cudaFuncAttributeMaxDynamicSharedMemorySize, SMEM_BYTES);

    k_init   <<<32, 256>>>(out, out_size);
    k_rmsnorm<<<dim3(SS / 64, BB), 256>>>(inputs, normw);
    k_router <<<BB, 128>>>(rw, rb);
    k_mixgT  <<<dim3(8192, 2), 256>>>(wgh);
    k_mixoT  <<<dim3(8192, 1), 256>>>(wout);
    k_gemm1  <<<dim3(DD2 / 256, SS / 128, BB), 256, SMEM_BYTES>>>(state);
    k_scanB  <<<(BB * DD) / 256, 256>>>();
    k_scanC  <<<(BB * NCH * DD) / 256, 256>>>(state, out, out_size);
    k_gemm2  <<<dim3(DD / 256, SS / 128, BB), 256, SMEM_BYTES>>>(inputs, out);
}

// round 8
// speedup vs baseline: 5.5189x; 1.0871x over previous
#include <cuda_runtime.h>
#include <cuda_fp16.h>
#include <cstdint>
#include <math.h>

#define BB   8
#define SS   4096
#define DD   1024
#define DD2  2048
#define CL   64
#define NCH  64
#define EPSV 1e-5f

// ---------------- scratch (device globals) -----------------------------------
__device__ __half g_xh[BB*SS*DD];                   // rmsnorm x fp16
__device__ __half g_wg[BB*DD2*DD];                  // mixed Wg^T (interleaved n) fp16
__device__ __half g_wo[BB*DD*DD];                   // mixed Wo^T fp16
__device__ __half g_hh[BB*SS*DD];                   // scan h fp16
__device__ __half2 g_ab[BB*SS*DD];                  // packed gates (a,b) fp16
__device__ float g_part[BB*64*DD];                  // per-block partial colsums
__device__ float g_probs [BB*3];
__device__ float g_cA[BB*NCH*DD], g_cB[BB*NCH*DD];

__device__ __forceinline__ float sigm(float x) { return 1.0f / (1.0f + __expf(-x)); }

__device__ __forceinline__ uint32_t cvta_smem(const void* p) {
    uint32_t a;
    asm("{ .reg .u64 t; cvta.to.shared.u64 t, %1; cvt.u32.u64 %0, t; }" : "=r"(a) : "l"(p));
    return a;
}

// ---------------- portable tensor-core primitives ------------------------------
__device__ __forceinline__ void mma16816(float* c, const uint32_t* a, const uint32_t* b) {
    asm volatile(
        "mma.sync.aligned.m16n8k16.row.col.f32.f16.f16.f32 "
        "{%0,%1,%2,%3},{%4,%5,%6,%7},{%8,%9},{%0,%1,%2,%3};"
        : "+f"(c[0]), "+f"(c[1]), "+f"(c[2]), "+f"(c[3])
        : "r"(a[0]), "r"(a[1]), "r"(a[2]), "r"(a[3]), "r"(b[0]), "r"(b[1]));
}
__device__ __forceinline__ void ldm4(uint32_t* r, uint32_t a) {
    asm volatile("ldmatrix.sync.aligned.m8n8.x4.shared.b16 {%0,%1,%2,%3}, [%4];"
        : "=r"(r[0]), "=r"(r[1]), "=r"(r[2]), "=r"(r[3]) : "r"(a));
}
#define CPA(s, g) asm volatile("cp.async.cg.shared.global [%0], [%1], 16;" :: "r"(s), "l"(g))
#define CP_COMMIT() asm volatile("cp.async.commit_group;")
#define CP_WAIT2()  asm volatile("cp.async.wait_group 2;")
#define CP_WAIT1()  asm volatile("cp.async.wait_group 1;")
#define CP_WAIT0()  asm volatile("cp.async.wait_group 0;")

// smem stage (BK=64, 128B rows, XOR-swizzled, no padding):
// A 128x128B | B 256x128B ; 4 stages = 192KB
#define A_BYTES    16384
#define STAGE_B    49152
#define SMEM_BYTES 196608

// swizzled byte offset within a matrix: row r (128B rows), 16B-chunk cc
#define SWZ(r, cc) ((r) * 128 + (((cc) ^ ((r) & 7)) << 4))

template<int ROWS>
__device__ __forceinline__ void load_mat(uint32_t sdst, const __half* g, int tid) {
#pragma unroll
    for (int it = 0; it < ROWS * 8 / 256; it++) {
        int idx = tid + it * 256;
        int r = idx >> 3, cc = idx & 7;
        CPA(sdst + SWZ(r, cc), g + (size_t)r * DD + cc * 8);
    }
}
__device__ __forceinline__ void load_stage(uint32_t sbuf,
    const __half* A, const __half* B, int k0, int tid) {
    load_mat<128>(sbuf,           A + k0, tid);
    load_mat<256>(sbuf + A_BYTES, B + k0, tid);
}

// 128x256 tile, 8 warps (2M x 4N), warp tile 64x64; fp16, BK=64, 4-stage pipe,
// fragment double-buffering across ks.
__device__ __forceinline__ void gemm_mainloop(
    float c[4][8][4], uint32_t sb,
    const __half* A, const __half* B, int tid) {

    int lane = tid & 31, wid = tid >> 5;
    int wm = wid >> 2, wn = wid & 3;
    int ra = wm * 64 + (lane & 15);              // A row (mf adds 16)
    int rb = wn * 64 + (lane & 7) + ((lane >> 4) << 3);  // B row (ng adds 16)
    int ca0 = lane >> 4;                          // A chunk base (ks adds 2)
    int cb0 = (lane >> 3) & 1;                    // B chunk base (ks adds 2)

    load_stage(sb,               A, B, 0,   tid); CP_COMMIT();
    load_stage(sb + STAGE_B,     A, B, 64,  tid); CP_COMMIT();
    load_stage(sb + 2 * STAGE_B, A, B, 128, tid); CP_COMMIT();

    uint32_t ah[2][4][4], bh[2][4][4];

#pragma unroll 1
    for (int s = 0; s < 16; s++) {
        if (s < 14) CP_WAIT2();
        else if (s == 14) CP_WAIT1();
        else CP_WAIT0();
        __syncthreads();
        if (s < 13) {
            load_stage(sb + ((s + 3) & 3) * STAGE_B, A, B, (s + 3) * 64, tid);
            CP_COMMIT();
        }
        uint32_t base  = sb + (s & 3) * STAGE_B;
        uint32_t baseB = base + A_BYTES;

        // prefetch ks=0 fragments
#pragma unroll
        for (int mf = 0; mf < 4; mf++) {
            int r = ra + mf * 16;
            ldm4(ah[0][mf], base + SWZ(r, ca0));
        }
#pragma unroll
        for (int ng = 0; ng < 4; ng++) {
            int r = rb + ng * 16;
            ldm4(bh[0][ng], baseB + SWZ(r, cb0));
        }
#pragma unroll
        for (int ks = 0; ks < 4; ks++) {
            int cur = ks & 1, nxt = cur ^ 1;
            if (ks < 3) {
                int can = ca0 + (ks + 1) * 2;
                int cbn = cb0 + (ks + 1) * 2;
#pragma unroll
                for (int mf = 0; mf < 4; mf++) {
                    int r = ra + mf * 16;
                    ldm4(ah[nxt][mf], base + SWZ(r, can));
                }
#pragma unroll
                for (int ng = 0; ng < 4; ng++) {
                    int r = rb + ng * 16;
                    ldm4(bh[nxt][ng], baseB + SWZ(r, cbn));
                }
            }
#pragma unroll
            for (int mf = 0; mf < 4; mf++)
#pragma unroll
                for (int nf = 0; nf < 8; nf++)
                    mma16816(c[mf][nf], ah[cur][mf], &bh[cur][nf >> 1][(nf & 1) * 2]);
        }
    }
    __syncthreads();
}

// ---------------- rmsnorm -> fp16 + per-block partial colsum ---------------------
__global__ void __launch_bounds__(256) k_rmsnorm(const float* __restrict__ inp,
                                                 const float* __restrict__ normw) {
    int b = blockIdx.y, t = threadIdx.x, warp = t >> 5, lane = t & 31;
    __shared__ float sw[DD];
    __shared__ float scs[DD];
    for (int i = t; i < DD; i += 256) { sw[i] = normw[i]; scs[i] = 0.0f; }
    __syncthreads();
    float csum[32];
#pragma unroll
    for (int k = 0; k < 32; k++) csum[k] = 0.0f;
    int s_base = blockIdx.x * 64;
#pragma unroll 1
    for (int r = 0; r < 8; r++) {
        int s = s_base + warp + r * 8;
        const float* row = inp + (size_t)(b * SS + s) * DD;
        float v[32], ss = 0.0f;
#pragma unroll
        for (int k = 0; k < 32; k++) { v[k] = row[lane + 32 * k]; ss += v[k] * v[k]; }
#pragma unroll
        for (int o = 16; o > 0; o >>= 1) ss += __shfl_xor_sync(0xffffffffu, ss, o);
        float inv = rsqrtf(ss * (1.0f / DD) + EPSV);
        size_t ro = (size_t)(b * SS + s) * DD;
#pragma unroll
        for (int k = 0; k < 32; k++) {
            float xv = v[k] * inv * sw[lane + 32 * k];
            g_xh[ro + lane + 32 * k] = __float2half_rn(xv);
            csum[k] += xv;
        }
    }
#pragma unroll
    for (int k = 0; k < 32; k++) atomicAdd(&scs[lane + 32 * k], csum[k]);
    __syncthreads();
    for (int i = t; i < DD; i += 256)
        g_part[((size_t)b * 64 + blockIdx.x) * DD + i] = scs[i];
}

// ---------------- router (reduces partials) + aux_loss ----------------------------
__global__ void k_router(const float* __restrict__ rw, const float* __restrict__ rb,
                         float* out, int out_size) {
    int b = blockIdx.x, t = threadIdx.x;
    if (b == 0 && t == 0 && out_size >= BB*SS*DD + BB*DD + 1)
        out[BB*SS*DD + BB*DD] = 0.0f;
    float p0 = 0, p1 = 0, p2 = 0;
    for (int d = t; d < DD; d += 128) {
        float cs = 0.0f;
        for (int blk = 0; blk < 64; blk++)
            cs += g_part[((size_t)b * 64 + blk) * DD + d];
        cs *= (1.0f / SS);
        p0 += cs * rw[d * 3 + 0];
        p1 += cs * rw[d * 3 + 1];
        p2 += cs * rw[d * 3 + 2];
    }
    __shared__ float sm[3][128];
    sm[0][t] = p0; sm[1][t] = p1; sm[2][t] = p2;
    __syncthreads();
    for (int o = 64; o > 0; o >>= 1) {
        if (t < o) { sm[0][t] += sm[0][t+o]; sm[1][t] += sm[1][t+o]; sm[2][t] += sm[2][t+o]; }
        __syncthreads();
    }
    if (t == 0) {
        float l0 = sm[0][0] + rb[0], l1 = sm[1][0] + rb[1], l2 = sm[2][0] + rb[2];
        float m = fmaxf(l0, fmaxf(l1, l2));
        float e0 = __expf(l0-m), e1 = __expf(l1-m), e2 = __expf(l2-m);
        float inv = 1.0f / (e0 + e1 + e2);
        g_probs[b*3+0] = e0*inv; g_probs[b*3+1] = e1*inv; g_probs[b*3+2] = e2*inv;
    }
}

// ---------------- mix + transpose Wg (interleaved n) -> fp16; b in fastest dim ---
__global__ void __launch_bounds__(256) k_mixgT(const float* __restrict__ wgh) {
    int b = blockIdx.x & 7;
    int tile = blockIdx.x >> 3;
    int which = blockIdx.y;
    int jt = tile & 31, kt2 = tile >> 5;
    int j0 = jt * 32, k0 = kt2 * 32;
    float p0 = g_probs[b*3+0], p1 = g_probs[b*3+1], p2 = g_probs[b*3+2];
    __shared__ float s[32][33];
    int c = threadIdx.x & 31, r = threadIdx.x >> 5;
#pragma unroll
    for (int rr = 0; rr < 4; rr++) {
        int k = k0 + r + 8 * rr;
        size_t o0 = (size_t)k * DD2 + (size_t)which * DD + j0 + c;
        s[r + 8*rr][c] = p0 * wgh[o0] + p1 * wgh[o0 + (size_t)DD*DD2] + p2 * wgh[o0 + (size_t)2*DD*DD2];
    }
    __syncthreads();
#pragma unroll
    for (int rr = 0; rr < 4; rr++) {
        int jl = r + 8 * rr, kl = c;
        size_t off = ((size_t)b * DD2 + 2*(j0+jl) + which) * DD + k0 + kl;
        g_wg[off] = __float2half_rn(s[kl][jl]);
    }
}

// ---------------- mix + transpose Wo -> fp16; b in fastest dim --------------------
__global__ void __launch_bounds__(256) k_mixoT(const float* __restrict__ wout) {
    int b = blockIdx.x & 7;
    int tile = blockIdx.x >> 3;
    int jt = tile & 31, kt2 = tile >> 5;
    int j0 = jt * 32, k0 = kt2 * 32;
    float p0 = g_probs[b*3+0], p1 = g_probs[b*3+1], p2 = g_probs[b*3+2];
    __shared__ float s[32][33];
    int c = threadIdx.x & 31, r = threadIdx.x >> 5;
#pragma unroll
    for (int rr = 0; rr < 4; rr++) {
        int k = k0 + r + 8 * rr;
        size_t o0 = (size_t)k * DD + j0 + c;
        s[r + 8*rr][c] = p0 * wout[o0] + p1 * wout[o0 + (size_t)DD*DD] + p2 * wout[o0 + (size_t)2*DD*DD];
    }
    __syncthreads();
#pragma unroll
    for (int rr = 0; rr < 4; rr++) {
        int jl = r + 8 * rr, kl = c;
        size_t off = ((size_t)b * DD + j0 + jl) * DD + k0 + kl;
        g_wo[off] = __float2half_rn(s[kl][jl]);
    }
}

// ---------------- GEMM1: hg = x @ Wg^T -> packed (a,b) + fused chunk-scan ---------
__global__ void __launch_bounds__(256, 1) k_gemm1(const float* __restrict__ state) {
    extern __shared__ __align__(128) char smraw[];
    uint32_t sb = cvta_smem(smraw);
    int tid = threadIdx.x;
    int b = blockIdx.z, m0 = blockIdx.y * 128, n0 = blockIdx.x * 256;

    const __half* A = g_xh + ((size_t)b * SS  + m0) * DD;
    const __half* B = g_wg + ((size_t)b * DD2 + n0) * DD;

    float c[4][8][4];
#pragma unroll
    for (int i = 0; i < 4; i++)
#pragma unroll
        for (int j = 0; j < 8; j++)
#pragma unroll
            for (int k = 0; k < 4; k++) c[i][j][k] = 0.0f;

    gemm_mainloop(c, sb, A, B, tid);

    // stage packed (a,b) half2 into smem (128 rows x 128 j, pitch 132)
    uint32_t* sab = (uint32_t*)smraw;
    int lane = tid & 31, wid = tid >> 5;
    int wm = wid >> 2, wn = wid & 3;
    int rloc = wm * 64 + (lane >> 2);
    int jloc = wn * 32 + (lane & 3);
#pragma unroll
    for (int mf = 0; mf < 4; mf++)
#pragma unroll
        for (int nf = 0; nf < 8; nf++)
#pragma unroll
            for (int hh2 = 0; hh2 < 2; hh2++) {
                float hid  = c[mf][nf][hh2 * 2];
                float gate = c[mf][nf][hh2 * 2 + 1];
                float z  = sigm(gate);
                float gg = (hid >= 0.0f) ? (hid + 0.5f) : sigm(hid);
                int r = rloc + mf * 16 + hh2 * 8;
                int j = jloc + nf * 4;
                __half2 v = __floats2half2_rn(1.0f - z, z * gg);
                sab[r * 132 + j] = *(uint32_t*)&v;
            }
    __syncthreads();

    // coalesced g_ab write
#pragma unroll
    for (int it = 0; it < 16; it++) {
        int idx = tid + it * 256;
        int row = idx >> 5, seg = idx & 31;
        size_t off = ((size_t)b * SS + m0 + row) * DD + (n0 >> 1) + seg * 4;
        uint4 v = *(uint4*)&sab[row * 132 + seg * 4];
        *(uint4*)&g_ab[off] = v;
    }

    // fused scanA: per-chunk (A,B) carries from smem (2 chunks x 128 d-pairs)
    {
        int chunk = tid >> 7, d = tid & 127;
        int cglob = (m0 >> 6) + chunk;
        int dglob = (n0 >> 1) + d;
        float Ac = 1.0f, Bc = 0.0f;
        const uint32_t* base = sab + chunk * 64 * 132 + d;
#pragma unroll 8
        for (int s = 0; s < CL; s++) {
            __half2 ab = *(const __half2*)&base[s * 132];
            float as = __low2float(ab);
            float bs = __high2float(ab);
            if (cglob == 0 && s == 0) bs += as * state[b * DD + dglob];
            Bc = fmaf(as, Bc, bs);
            Ac *= as;
        }
        int off = (b * NCH + cglob) * DD + dglob;
        g_cA[off] = Ac;
        g_cB[off] = Bc;
    }
}

// ---------------- GEMM2: out = h @ Wo^T + inputs ------------------------------------
__global__ void __launch_bounds__(256, 1) k_gemm2(const float* __restrict__ inputs,
                                                  float* __restrict__ out) {
    extern __shared__ __align__(128) char smraw[];
    uint32_t sb = cvta_smem(smraw);
    int tid = threadIdx.x;
    int b = blockIdx.z, m0 = blockIdx.y * 128, n0 = blockIdx.x * 256;

    const __half* A = g_hh + ((size_t)b * SS + m0) * DD;
    const __half* B = g_wo + ((size_t)b * DD + n0) * DD;

    float c[4][8][4];
#pragma unroll
    for (int i = 0; i < 4; i++)
#pragma unroll
        for (int j = 0; j < 8; j++)
#pragma unroll
            for (int k = 0; k < 4; k++) c[i][j][k] = 0.0f;

    gemm_mainloop(c, sb, A, B, tid);

    int lane = tid & 31, wid = tid >> 5;
    int wm = wid >> 2, wn = wid & 3;
    int rbase = m0 + wm * 64 + (lane >> 2);
    int cbase = n0 + wn * 64 + (lane & 3) * 2;
#pragma unroll
    for (int mf = 0; mf < 4; mf++)
#pragma unroll
        for (int nf = 0; nf < 8; nf++)
#pragma unroll
            for (int hh2 = 0; hh2 < 2; hh2++) {
                int row = rbase + mf * 16 + hh2 * 8;
                int col = cbase + nf * 8;
                size_t off = ((size_t)b * SS + row) * DD + col;
                float2 iv = *(const float2*)&inputs[off];
                float2 ov;
                ov.x = c[mf][nf][hh2 * 2]     + iv.x;
                ov.y = c[mf][nf][hh2 * 2 + 1] + iv.y;
                *(float2*)&out[off] = ov;
            }
}

// ---------------- scan (B: chunk carries; C: apply + h fp16) -----------------------
__global__ void k_scanB() {
    int idx = blockIdx.x * 256 + threadIdx.x;
    int d = idx & (DD - 1);
    int b = idx >> 10;
    float h = 0.0f;
    for (int c = 0; c < NCH; c++) {
        int off = (b * NCH + c) * DD + d;
        float A = g_cA[off], Bc = g_cB[off];
        g_cB[off] = h;
        h = fmaf(A, h, Bc);
    }
}

__global__ void k_scanC(const float* __restrict__ state, float* out, int out_size) {
    int idx = blockIdx.x * 256 + threadIdx.x;
    int d = idx & (DD - 1);
    int c = (idx >> 10) & (NCH - 1);
    int b = idx >> 16;
    size_t base = (size_t)(b * SS + c * CL) * DD + d;
    float h = g_cB[idx];
#pragma unroll 8
    for (int s = 0; s < CL; s++) {
        __half2 ab = g_ab[base + (size_t)s * DD];
        float as = __low2float(ab);
        float bs = __high2float(ab);
        if (c == 0 && s == 0) bs += as * state[b * DD + d];
        h = fmaf(as, h, bs);
        g_hh[base + (size_t)s * DD] = __float2half_rn(h);
    }
    if (c == NCH - 1 && out_size >= BB*SS*DD + BB*DD)
        out[BB*SS*DD + b * DD + d] = h;
}

// ---------------- launch ------------------------------------------------------------
extern "C" void kernel_launch(void* const* d_in, const int* in_sizes, int n_in,
                              void* d_out, int out_size) {
    const float* inputs = (const float*)d_in[0];
    const float* state  = (const float*)d_in[1];
    const float* normw  = (const float*)d_in[2];
    const float* rw     = (const float*)d_in[3];
    const float* rb     = (const float*)d_in[4];
    const float* wgh    = (const float*)d_in[5];
    const float* wout   = (const float*)d_in[6];
    float* out = (float*)d_out;

    cudaFuncSetAttribute(k_gemm1, cudaFuncAttributeMaxDynamicSharedMemorySize, SMEM_BYTES);
    cudaFuncSetAttribute(k_gemm2, cudaFuncAttributeMaxDynamicSharedMemorySize, SMEM_BYTES);

    k_rmsnorm<<<dim3(SS / 64, BB), 256>>>(inputs, normw);
    k_router <<<BB, 128>>>(rw, rb, out, out_size);
    k_mixgT  <<<dim3(8192, 2), 256>>>(wgh);
    k_gemm1  <<<dim3(DD2 / 256, SS / 128, BB), 256, SMEM_BYTES>>>(state);
    k_mixoT  <<<dim3(8192, 1), 256>>>(wout);
    k_scanB  <<<(BB * DD) / 256, 256>>>();
    k_scanC  <<<(BB * NCH * DD) / 256, 256>>>(state, out, out_size);
    k_gemm2  <<<dim3(DD / 256, SS / 128, BB), 256, SMEM_BYTES>>>(inputs, out);
}

// round 9
// speedup vs baseline: 6.0134x; 1.0896x over previous
#include <cuda_runtime.h>
#include <cuda_fp16.h>
#include <cstdint>
#include <math.h>

#define BB   8
#define SS   4096
#define DD   1024
#define DD2  2048
#define CL   64
#define NCH  64
#define EPSV 1e-5f

// ---------------- scratch (device globals) -----------------------------------
__device__ __half g_xh[BB*SS*DD];                   // rmsnorm x fp16
__device__ __half g_wg[BB*DD2*DD];                  // mixed Wg^T (interleaved n) fp16
__device__ __half g_wo[BB*DD*DD];                   // mixed Wo^T fp16
__device__ __half g_hh[BB*SS*DD];                   // scan h fp16
__device__ __half2 g_ab[BB*SS*DD];                  // packed gates (a,b) fp16
__device__ float g_part[BB*64*DD];                  // per-block partial colsums
__device__ float g_probs [BB*3];
__device__ float g_cA[BB*NCH*DD], g_cB[BB*NCH*DD];

__device__ __forceinline__ float sigm(float x) { return 1.0f / (1.0f + __expf(-x)); }

__device__ __forceinline__ uint32_t cvta_smem(const void* p) {
    uint32_t a;
    asm("{ .reg .u64 t; cvta.to.shared.u64 t, %1; cvt.u32.u64 %0, t; }" : "=r"(a) : "l"(p));
    return a;
}

// ---------------- portable tensor-core primitives ------------------------------
__device__ __forceinline__ void mma16816(float* c, const uint32_t* a, const uint32_t* b) {
    asm volatile(
        "mma.sync.aligned.m16n8k16.row.col.f32.f16.f16.f32 "
        "{%0,%1,%2,%3},{%4,%5,%6,%7},{%8,%9},{%0,%1,%2,%3};"
        : "+f"(c[0]), "+f"(c[1]), "+f"(c[2]), "+f"(c[3])
        : "r"(a[0]), "r"(a[1]), "r"(a[2]), "r"(a[3]), "r"(b[0]), "r"(b[1]));
}
__device__ __forceinline__ void ldm4(uint32_t* r, uint32_t a) {
    asm volatile("ldmatrix.sync.aligned.m8n8.x4.shared.b16 {%0,%1,%2,%3}, [%4];"
        : "=r"(r[0]), "=r"(r[1]), "=r"(r[2]), "=r"(r[3]) : "r"(a));
}
#define CPA(s, g) asm volatile("cp.async.cg.shared.global [%0], [%1], 16;" :: "r"(s), "l"(g))
#define CP_COMMIT() asm volatile("cp.async.commit_group;")
#define CP_WAIT2()  asm volatile("cp.async.wait_group 2;")
#define CP_WAIT1()  asm volatile("cp.async.wait_group 1;")
#define CP_WAIT0()  asm volatile("cp.async.wait_group 0;")

#define NT 512     // threads per GEMM CTA (16 warps, 4 per SMSP)

// smem stage (BK=64, 128B rows, XOR-swizzled): A 128x128B | B 256x128B ; 4 stages
#define A_BYTES    16384
#define STAGE_B    49152
#define SMEM_BYTES 196608

// swizzled byte offset within a matrix: row r (128B rows), 16B-chunk cc
#define SWZ(r, cc) ((r) * 128 + (((cc) ^ ((r) & 7)) << 4))

template<int ROWS>
__device__ __forceinline__ void load_mat(uint32_t sdst, const __half* g, int tid) {
#pragma unroll
    for (int it = 0; it < ROWS * 8 / NT; it++) {
        int idx = tid + it * NT;
        int r = idx >> 3, cc = idx & 7;
        CPA(sdst + SWZ(r, cc), g + (size_t)r * DD + cc * 8);
    }
}
__device__ __forceinline__ void load_stage(uint32_t sbuf,
    const __half* A, const __half* B, int k0, int tid) {
    load_mat<128>(sbuf,           A + k0, tid);
    load_mat<256>(sbuf + A_BYTES, B + k0, tid);
}

// 128x256 CTA tile, 16 warps (2M x 8N), warp tile 64x32; fp16, BK=64, 4-stage pipe.
__device__ __forceinline__ void gemm_mainloop(
    float c[4][4][4], uint32_t sb,
    const __half* A, const __half* B, int tid) {

    int lane = tid & 31, wid = tid >> 5;
    int wm = wid >> 3, wn = wid & 7;
    int ra = wm * 64 + (lane & 15);                      // A row (mf adds 16)
    int rb = wn * 32 + (lane & 7) + ((lane >> 4) << 3);  // B row (ng adds 16)
    int ca0 = lane >> 4;                                 // A chunk base (ks adds 2)
    int cb0 = (lane >> 3) & 1;                           // B chunk base (ks adds 2)

    load_stage(sb,               A, B, 0,   tid); CP_COMMIT();
    load_stage(sb + STAGE_B,     A, B, 64,  tid); CP_COMMIT();
    load_stage(sb + 2 * STAGE_B, A, B, 128, tid); CP_COMMIT();

#pragma unroll 1
    for (int s = 0; s < 16; s++) {
        if (s < 14) CP_WAIT2();
        else if (s == 14) CP_WAIT1();
        else CP_WAIT0();
        __syncthreads();
        if (s < 13) {
            load_stage(sb + ((s + 3) & 3) * STAGE_B, A, B, (s + 3) * 64, tid);
            CP_COMMIT();
        }
        uint32_t base  = sb + (s & 3) * STAGE_B;
        uint32_t baseB = base + A_BYTES;
#pragma unroll
        for (int ks = 0; ks < 4; ks++) {
            uint32_t ah[4][4], bh[2][4];
#pragma unroll
            for (int mf = 0; mf < 4; mf++)
                ldm4(ah[mf], base + SWZ(ra + mf * 16, ca0 + ks * 2));
#pragma unroll
            for (int ng = 0; ng < 2; ng++)
                ldm4(bh[ng], baseB + SWZ(rb + ng * 16, cb0 + ks * 2));
#pragma unroll
            for (int mf = 0; mf < 4; mf++)
#pragma unroll
                for (int nf = 0; nf < 4; nf++)
                    mma16816(c[mf][nf], ah[mf], &bh[nf >> 1][(nf & 1) * 2]);
        }
    }
    __syncthreads();
}

// ---------------- rmsnorm -> fp16 + per-block partial colsum ---------------------
__global__ void __launch_bounds__(256) k_rmsnorm(const float* __restrict__ inp,
                                                 const float* __restrict__ normw) {
    int b = blockIdx.y, t = threadIdx.x, warp = t >> 5, lane = t & 31;
    __shared__ float sw[DD];
    __shared__ float scs[DD];
    for (int i = t; i < DD; i += 256) { sw[i] = normw[i]; scs[i] = 0.0f; }
    __syncthreads();
    float csum[32];
#pragma unroll
    for (int k = 0; k < 32; k++) csum[k] = 0.0f;
    int s_base = blockIdx.x * 64;
#pragma unroll 1
    for (int r = 0; r < 8; r++) {
        int s = s_base + warp + r * 8;
        const float* row = inp + (size_t)(b * SS + s) * DD;
        float v[32], ss = 0.0f;
#pragma unroll
        for (int k = 0; k < 32; k++) { v[k] = row[lane + 32 * k]; ss += v[k] * v[k]; }
#pragma unroll
        for (int o = 16; o > 0; o >>= 1) ss += __shfl_xor_sync(0xffffffffu, ss, o);
        float inv = rsqrtf(ss * (1.0f / DD) + EPSV);
        size_t ro = (size_t)(b * SS + s) * DD;
#pragma unroll
        for (int k = 0; k < 32; k++) {
            float xv = v[k] * inv * sw[lane + 32 * k];
            g_xh[ro + lane + 32 * k] = __float2half_rn(xv);
            csum[k] += xv;
        }
    }
#pragma unroll
    for (int k = 0; k < 32; k++) atomicAdd(&scs[lane + 32 * k], csum[k]);
    __syncthreads();
    for (int i = t; i < DD; i += 256)
        g_part[((size_t)b * 64 + blockIdx.x) * DD + i] = scs[i];
}

// ---------------- router (reduces partials) + aux_loss ----------------------------
__global__ void k_router(const float* __restrict__ rw, const float* __restrict__ rb,
                         float* out, int out_size) {
    int b = blockIdx.x, t = threadIdx.x;
    if (b == 0 && t == 0 && out_size >= BB*SS*DD + BB*DD + 1)
        out[BB*SS*DD + BB*DD] = 0.0f;
    float p0 = 0, p1 = 0, p2 = 0;
    for (int d = t; d < DD; d += 128) {
        float cs = 0.0f;
        for (int blk = 0; blk < 64; blk++)
            cs += g_part[((size_t)b * 64 + blk) * DD + d];
        cs *= (1.0f / SS);
        p0 += cs * rw[d * 3 + 0];
        p1 += cs * rw[d * 3 + 1];
        p2 += cs * rw[d * 3 + 2];
    }
    __shared__ float sm[3][128];
    sm[0][t] = p0; sm[1][t] = p1; sm[2][t] = p2;
    __syncthreads();
    for (int o = 64; o > 0; o >>= 1) {
        if (t < o) { sm[0][t] += sm[0][t+o]; sm[1][t] += sm[1][t+o]; sm[2][t] += sm[2][t+o]; }
        __syncthreads();
    }
    if (t == 0) {
        float l0 = sm[0][0] + rb[0], l1 = sm[1][0] + rb[1], l2 = sm[2][0] + rb[2];
        float m = fmaxf(l0, fmaxf(l1, l2));
        float e0 = __expf(l0-m), e1 = __expf(l1-m), e2 = __expf(l2-m);
        float inv = 1.0f / (e0 + e1 + e2);
        g_probs[b*3+0] = e0*inv; g_probs[b*3+1] = e1*inv; g_probs[b*3+2] = e2*inv;
    }
}

// ---------------- mix + transpose Wg (interleaved n) -> fp16; b in fastest dim ---
__global__ void __launch_bounds__(256) k_mixgT(const float* __restrict__ wgh) {
    int b = blockIdx.x & 7;
    int tile = blockIdx.x >> 3;
    int which = blockIdx.y;
    int jt = tile & 31, kt2 = tile >> 5;
    int j0 = jt * 32, k0 = kt2 * 32;
    float p0 = g_probs[b*3+0], p1 = g_probs[b*3+1], p2 = g_probs[b*3+2];
    __shared__ float s[32][33];
    int c = threadIdx.x & 31, r = threadIdx.x >> 5;
#pragma unroll
    for (int rr = 0; rr < 4; rr++) {
        int k = k0 + r + 8 * rr;
        size_t o0 = (size_t)k * DD2 + (size_t)which * DD + j0 + c;
        s[r + 8*rr][c] = p0 * wgh[o0] + p1 * wgh[o0 + (size_t)DD*DD2] + p2 * wgh[o0 + (size_t)2*DD*DD2];
    }
    __syncthreads();
#pragma unroll
    for (int rr = 0; rr < 4; rr++) {
        int jl = r + 8 * rr, kl = c;
        size_t off = ((size_t)b * DD2 + 2*(j0+jl) + which) * DD + k0 + kl;
        g_wg[off] = __float2half_rn(s[kl][jl]);
    }
}

// ---------------- mix + transpose Wo -> fp16; b in fastest dim --------------------
__global__ void __launch_bounds__(256) k_mixoT(const float* __restrict__ wout) {
    int b = blockIdx.x & 7;
    int tile = blockIdx.x >> 3;
    int jt = tile & 31, kt2 = tile >> 5;
    int j0 = jt * 32, k0 = kt2 * 32;
    float p0 = g_probs[b*3+0], p1 = g_probs[b*3+1], p2 = g_probs[b*3+2];
    __shared__ float s[32][33];
    int c = threadIdx.x & 31, r = threadIdx.x >> 5;
#pragma unroll
    for (int rr = 0; rr < 4; rr++) {
        int k = k0 + r + 8 * rr;
        size_t o0 = (size_t)k * DD + j0 + c;
        s[r + 8*rr][c] = p0 * wout[o0] + p1 * wout[o0 + (size_t)DD*DD] + p2 * wout[o0 + (size_t)2*DD*DD];
    }
    __syncthreads();
#pragma unroll
    for (int rr = 0; rr < 4; rr++) {
        int jl = r + 8 * rr, kl = c;
        size_t off = ((size_t)b * DD + j0 + jl) * DD + k0 + kl;
        g_wo[off] = __float2half_rn(s[kl][jl]);
    }
}

// ---------------- GEMM1: hg = x @ Wg^T -> packed (a,b) + fused chunk-scan ---------
__global__ void __launch_bounds__(NT, 1) k_gemm1(const float* __restrict__ state) {
    extern __shared__ __align__(128) char smraw[];
    uint32_t sb = cvta_smem(smraw);
    int tid = threadIdx.x;
    int b = blockIdx.z, m0 = blockIdx.y * 128, n0 = blockIdx.x * 256;

    const __half* A = g_xh + ((size_t)b * SS  + m0) * DD;
    const __half* B = g_wg + ((size_t)b * DD2 + n0) * DD;

    float c[4][4][4];
#pragma unroll
    for (int i = 0; i < 4; i++)
#pragma unroll
        for (int j = 0; j < 4; j++)
#pragma unroll
            for (int k = 0; k < 4; k++) c[i][j][k] = 0.0f;

    gemm_mainloop(c, sb, A, B, tid);

    // stage packed (a,b) half2 into smem (128 rows x 128 j, pitch 132)
    uint32_t* sab = (uint32_t*)smraw;
    int lane = tid & 31, wid = tid >> 5;
    int wm = wid >> 3, wn = wid & 7;
    int rloc = wm * 64 + (lane >> 2);
    int jloc = wn * 16 + (lane & 3);
#pragma unroll
    for (int mf = 0; mf < 4; mf++)
#pragma unroll
        for (int nf = 0; nf < 4; nf++)
#pragma unroll
            for (int hh2 = 0; hh2 < 2; hh2++) {
                float hid  = c[mf][nf][hh2 * 2];
                float gate = c[mf][nf][hh2 * 2 + 1];
                float z  = sigm(gate);
                float gg = (hid >= 0.0f) ? (hid + 0.5f) : sigm(hid);
                int r = rloc + mf * 16 + hh2 * 8;
                int j = jloc + nf * 4;
                __half2 v = __floats2half2_rn(1.0f - z, z * gg);
                sab[r * 132 + j] = *(uint32_t*)&v;
            }
    __syncthreads();

    // coalesced g_ab write (4096 uint4 over 512 threads)
#pragma unroll
    for (int it = 0; it < 8; it++) {
        int idx = tid + it * NT;
        int row = idx >> 5, seg = idx & 31;
        size_t off = ((size_t)b * SS + m0 + row) * DD + (n0 >> 1) + seg * 4;
        uint4 v = *(uint4*)&sab[row * 132 + seg * 4];
        *(uint4*)&g_ab[off] = v;
    }

    // fused scanA: per-chunk (A,B) carries from smem (2 chunks x 128 d-pairs)
    if (tid < 256) {
        int chunk = tid >> 7, d = tid & 127;
        int cglob = (m0 >> 6) + chunk;
        int dglob = (n0 >> 1) + d;
        float Ac = 1.0f, Bc = 0.0f;
        const uint32_t* base = sab + chunk * 64 * 132 + d;
#pragma unroll 8
        for (int s = 0; s < CL; s++) {
            __half2 ab = *(const __half2*)&base[s * 132];
            float as = __low2float(ab);
            float bs = __high2float(ab);
            if (cglob == 0 && s == 0) bs += as * state[b * DD + dglob];
            Bc = fmaf(as, Bc, bs);
            Ac *= as;
        }
        int off = (b * NCH + cglob) * DD + dglob;
        g_cA[off] = Ac;
        g_cB[off] = Bc;
    }
}

// ---------------- GEMM2: out = h @ Wo^T + inputs ------------------------------------
__global__ void __launch_bounds__(NT, 1) k_gemm2(const float* __restrict__ inputs,
                                                 float* __restrict__ out) {
    extern __shared__ __align__(128) char smraw[];
    uint32_t sb = cvta_smem(smraw);
    int tid = threadIdx.x;
    int b = blockIdx.z, m0 = blockIdx.y * 128, n0 = blockIdx.x * 256;

    const __half* A = g_hh + ((size_t)b * SS + m0) * DD;
    const __half* B = g_wo + ((size_t)b * DD + n0) * DD;

    float c[4][4][4];
#pragma unroll
    for (int i = 0; i < 4; i++)
#pragma unroll
        for (int j = 0; j < 4; j++)
#pragma unroll
            for (int k = 0; k < 4; k++) c[i][j][k] = 0.0f;

    gemm_mainloop(c, sb, A, B, tid);

    int lane = tid & 31, wid = tid >> 5;
    int wm = wid >> 3, wn = wid & 7;
    int rbase = m0 + wm * 64 + (lane >> 2);
    int cbase = n0 + wn * 32 + (lane & 3) * 2;
#pragma unroll
    for (int mf = 0; mf < 4; mf++)
#pragma unroll
        for (int nf = 0; nf < 4; nf++)
#pragma unroll
            for (int hh2 = 0; hh2 < 2; hh2++) {
                int row = rbase + mf * 16 + hh2 * 8;
                int col = cbase + nf * 8;
                size_t off = ((size_t)b * SS + row) * DD + col;
                float2 iv = *(const float2*)&inputs[off];
                float2 ov;
                ov.x = c[mf][nf][hh2 * 2]     + iv.x;
                ov.y = c[mf][nf][hh2 * 2 + 1] + iv.y;
                *(float2*)&out[off] = ov;
            }
}

// ---------------- scan (B: chunk carries; C: apply + h fp16) -----------------------
__global__ void k_scanB() {
    int idx = blockIdx.x * 256 + threadIdx.x;
    int d = idx & (DD - 1);
    int b = idx >> 10;
    float h = 0.0f;
    for (int c = 0; c < NCH; c++) {
        int off = (b * NCH + c) * DD + d;
        float A = g_cA[off], Bc = g_cB[off];
        g_cB[off] = h;
        h = fmaf(A, h, Bc);
    }
}

__global__ void k_scanC(const float* __restrict__ state, float* out, int out_size) {
    int idx = blockIdx.x * 256 + threadIdx.x;
    int d = idx & (DD - 1);
    int c = (idx >> 10) & (NCH - 1);
    int b = idx >> 16;
    size_t base = (size_t)(b * SS + c * CL) * DD + d;
    float h = g_cB[idx];
#pragma unroll 8
    for (int s = 0; s < CL; s++) {
        __half2 ab = g_ab[base + (size_t)s * DD];
        float as = __low2float(ab);
        float bs = __high2float(ab);
        if (c == 0 && s == 0) bs += as * state[b * DD + d];
        h = fmaf(as, h, bs);
        g_hh[base + (size_t)s * DD] = __float2half_rn(h);
    }
    if (c == NCH - 1 && out_size >= BB*SS*DD + BB*DD)
        out[BB*SS*DD + b * DD + d] = h;
}

// ---------------- launch ------------------------------------------------------------
extern "C" void kernel_launch(void* const* d_in, const int* in_sizes, int n_in,
                              void* d_out, int out_size) {
    const float* inputs = (const float*)d_in[0];
    const float* state  = (const float*)d_in[1];
    const float* normw  = (const float*)d_in[2];
    const float* rw     = (const float*)d_in[3];
    const float* rb     = (const float*)d_in[4];
    const float* wgh    = (const float*)d_in[5];
    const float* wout   = (const float*)d_in[6];
    float* out = (float*)d_out;

    cudaFuncSetAttribute(k_gemm1, cudaFuncAttributeMaxDynamicSharedMemorySize, SMEM_BYTES);
    cudaFuncSetAttribute(k_gemm2, cudaFuncAttributeMaxDynamicSharedMemorySize, SMEM_BYTES);

    k_rmsnorm<<<dim3(SS / 64, BB), 256>>>(inputs, normw);
    k_router <<<BB, 128>>>(rw, rb, out, out_size);
    k_mixgT  <<<dim3(8192, 2), 256>>>(wgh);
    k_gemm1  <<<dim3(DD2 / 256, SS / 128, BB), NT, SMEM_BYTES>>>(state);
    k_mixoT  <<<dim3(8192, 1), 256>>>(wout);
    k_scanB  <<<(BB * DD) / 256, 256>>>();
    k_scanC  <<<(BB * NCH * DD) / 256, 256>>>(state, out, out_size);
    k_gemm2  <<<dim3(DD / 256, SS / 128, BB), NT, SMEM_BYTES>>>(inputs, out);
}

// round 10
// speedup vs baseline: 6.5250x; 1.0851x over previous
#include <cuda_runtime.h>
#include <cuda_fp16.h>
#include <cstdint>
#include <math.h>

#define BB   8
#define SS   4096
#define DD   1024
#define DD2  2048
#define CL   64
#define NCH  64
#define EPSV 1e-5f

// ---------------- scratch (device globals) -----------------------------------
__device__ __half g_xh[BB*SS*DD];                   // rmsnorm x fp16
__device__ __half g_wg[BB*DD2*DD];                  // mixed Wg^T (interleaved n) fp16
__device__ __half g_wo[BB*DD*DD];                   // mixed Wo^T fp16
__device__ __half g_hh[BB*SS*DD];                   // scan h fp16
__device__ __half2 g_ab[BB*SS*DD];                  // packed gates (a,b) fp16
__device__ float g_part[BB*64*DD];                  // per-block partial colsums
__device__ float g_probs [BB*3];
__device__ float g_cA[BB*NCH*DD], g_cB[BB*NCH*DD];

__device__ __forceinline__ float sigm(float x) { return 1.0f / (1.0f + __expf(-x)); }

__device__ __forceinline__ uint32_t cvta_smem(const void* p) {
    uint32_t a;
    asm("{ .reg .u64 t; cvta.to.shared.u64 t, %1; cvt.u32.u64 %0, t; }" : "=r"(a) : "l"(p));
    return a;
}

// ---------------- portable tensor-core primitives ------------------------------
__device__ __forceinline__ void mma16816(float* c, const uint32_t* a, const uint32_t* b) {
    asm volatile(
        "mma.sync.aligned.m16n8k16.row.col.f32.f16.f16.f32 "
        "{%0,%1,%2,%3},{%4,%5,%6,%7},{%8,%9},{%0,%1,%2,%3};"
        : "+f"(c[0]), "+f"(c[1]), "+f"(c[2]), "+f"(c[3])
        : "r"(a[0]), "r"(a[1]), "r"(a[2]), "r"(a[3]), "r"(b[0]), "r"(b[1]));
}
__device__ __forceinline__ void ldm4(uint32_t* r, uint32_t a) {
    asm volatile("ldmatrix.sync.aligned.m8n8.x4.shared.b16 {%0,%1,%2,%3}, [%4];"
        : "=r"(r[0]), "=r"(r[1]), "=r"(r[2]), "=r"(r[3]) : "r"(a));
}
#define CPA(s, g) asm volatile("cp.async.cg.shared.global [%0], [%1], 16;" :: "r"(s), "l"(g))
#define CP_COMMIT() asm volatile("cp.async.commit_group;")
#define CP_WAIT1()  asm volatile("cp.async.wait_group 1;")
#define CP_WAIT0()  asm volatile("cp.async.wait_group 0;")

#define NT 256     // threads per GEMM CTA (8 warps); 2 CTAs per SM

// smem stage (BK=64, 128B rows, XOR-swizzled): A 128x128B | B 128x128B ; 3 stages
#define A_BYTES    16384
#define STAGE_B    32768
#define SMEM_BYTES 98304

// swizzled byte offset within a matrix: row r (128B rows), 16B-chunk cc
#define SWZ(r, cc) ((r) * 128 + (((cc) ^ ((r) & 7)) << 4))

template<int ROWS>
__device__ __forceinline__ void load_mat(uint32_t sdst, const __half* g, int tid) {
#pragma unroll
    for (int it = 0; it < ROWS * 8 / NT; it++) {
        int idx = tid + it * NT;
        int r = idx >> 3, cc = idx & 7;
        CPA(sdst + SWZ(r, cc), g + (size_t)r * DD + cc * 8);
    }
}
__device__ __forceinline__ void load_stage(uint32_t sbuf,
    const __half* A, const __half* B, int k0, int tid) {
    load_mat<128>(sbuf,           A + k0, tid);
    load_mat<128>(sbuf + A_BYTES, B + k0, tid);
}

// 128x128 CTA tile, 8 warps (2M x 4N), warp tile 64x32; fp16, BK=64, 3-stage pipe.
__device__ __forceinline__ void gemm_mainloop(
    float c[4][4][4], uint32_t sb,
    const __half* A, const __half* B, int tid) {

    int lane = tid & 31, wid = tid >> 5;
    int wm = wid >> 2, wn = wid & 3;
    int ra = wm * 64 + (lane & 15);                      // A row (mf adds 16)
    int rb = wn * 32 + (lane & 7) + ((lane >> 4) << 3);  // B row (ng adds 16)
    int ca0 = lane >> 4;                                 // A chunk base (ks adds 2)
    int cb0 = (lane >> 3) & 1;                           // B chunk base (ks adds 2)

    load_stage(sb,           A, B, 0,  tid); CP_COMMIT();
    load_stage(sb + STAGE_B, A, B, 64, tid); CP_COMMIT();

    uint32_t bufs[3] = { sb, sb + STAGE_B, sb + 2 * STAGE_B };

#pragma unroll 1
    for (int s = 0; s < 16; s++) {
        if (s < 15) CP_WAIT1(); else CP_WAIT0();
        __syncthreads();
        if (s < 14) {
            load_stage(bufs[(s + 2) % 3], A, B, (s + 2) * 64, tid);
            CP_COMMIT();
        }
        uint32_t base  = bufs[s % 3];
        uint32_t baseB = base + A_BYTES;
#pragma unroll
        for (int ks = 0; ks < 4; ks++) {
            uint32_t ah[4][4], bh[2][4];
#pragma unroll
            for (int mf = 0; mf < 4; mf++)
                ldm4(ah[mf], base + SWZ(ra + mf * 16, ca0 + ks * 2));
#pragma unroll
            for (int ng = 0; ng < 2; ng++)
                ldm4(bh[ng], baseB + SWZ(rb + ng * 16, cb0 + ks * 2));
#pragma unroll
            for (int mf = 0; mf < 4; mf++)
#pragma unroll
                for (int nf = 0; nf < 4; nf++)
                    mma16816(c[mf][nf], ah[mf], &bh[nf >> 1][(nf & 1) * 2]);
        }
    }
    __syncthreads();
}

// ---------------- rmsnorm -> fp16 + per-block partial colsum ---------------------
__global__ void __launch_bounds__(256) k_rmsnorm(const float* __restrict__ inp,
                                                 const float* __restrict__ normw) {
    int b = blockIdx.y, t = threadIdx.x, warp = t >> 5, lane = t & 31;
    __shared__ float sw[DD];
    __shared__ float scs[DD];
    for (int i = t; i < DD; i += 256) { sw[i] = normw[i]; scs[i] = 0.0f; }
    __syncthreads();
    float csum[32];
#pragma unroll
    for (int k = 0; k < 32; k++) csum[k] = 0.0f;
    int s_base = blockIdx.x * 64;
#pragma unroll 1
    for (int r = 0; r < 8; r++) {
        int s = s_base + warp + r * 8;
        const float* row = inp + (size_t)(b * SS + s) * DD;
        float v[32], ss = 0.0f;
#pragma unroll
        for (int k = 0; k < 32; k++) { v[k] = row[lane + 32 * k]; ss += v[k] * v[k]; }
#pragma unroll
        for (int o = 16; o > 0; o >>= 1) ss += __shfl_xor_sync(0xffffffffu, ss, o);
        float inv = rsqrtf(ss * (1.0f / DD) + EPSV);
        size_t ro = (size_t)(b * SS + s) * DD;
#pragma unroll
        for (int k = 0; k < 32; k++) {
            float xv = v[k] * inv * sw[lane + 32 * k];
            g_xh[ro + lane + 32 * k] = __float2half_rn(xv);
            csum[k] += xv;
        }
    }
#pragma unroll
    for (int k = 0; k < 32; k++) atomicAdd(&scs[lane + 32 * k], csum[k]);
    __syncthreads();
    for (int i = t; i < DD; i += 256)
        g_part[((size_t)b * 64 + blockIdx.x) * DD + i] = scs[i];
}

// ---------------- router (reduces partials) + aux_loss ----------------------------
__global__ void k_router(const float* __restrict__ rw, const float* __restrict__ rb,
                         float* out, int out_size) {
    int b = blockIdx.x, t = threadIdx.x;
    if (b == 0 && t == 0 && out_size >= BB*SS*DD + BB*DD + 1)
        out[BB*SS*DD + BB*DD] = 0.0f;
    float p0 = 0, p1 = 0, p2 = 0;
    for (int d = t; d < DD; d += 128) {
        float cs = 0.0f;
        for (int blk = 0; blk < 64; blk++)
            cs += g_part[((size_t)b * 64 + blk) * DD + d];
        cs *= (1.0f / SS);
        p0 += cs * rw[d * 3 + 0];
        p1 += cs * rw[d * 3 + 1];
        p2 += cs * rw[d * 3 + 2];
    }
    __shared__ float sm[3][128];
    sm[0][t] = p0; sm[1][t] = p1; sm[2][t] = p2;
    __syncthreads();
    for (int o = 64; o > 0; o >>= 1) {
        if (t < o) { sm[0][t] += sm[0][t+o]; sm[1][t] += sm[1][t+o]; sm[2][t] += sm[2][t+o]; }
        __syncthreads();
    }
    if (t == 0) {
        float l0 = sm[0][0] + rb[0], l1 = sm[1][0] + rb[1], l2 = sm[2][0] + rb[2];
        float m = fmaxf(l0, fmaxf(l1, l2));
        float e0 = __expf(l0-m), e1 = __expf(l1-m), e2 = __expf(l2-m);
        float inv = 1.0f / (e0 + e1 + e2);
        g_probs[b*3+0] = e0*inv; g_probs[b*3+1] = e1*inv; g_probs[b*3+2] = e2*inv;
    }
}

// ---------------- mix + transpose Wg (interleaved n) -> fp16; b in fastest dim ---
__global__ void __launch_bounds__(256) k_mixgT(const float* __restrict__ wgh) {
    int b = blockIdx.x & 7;
    int tile = blockIdx.x >> 3;
    int which = blockIdx.y;
    int jt = tile & 31, kt2 = tile >> 5;
    int j0 = jt * 32, k0 = kt2 * 32;
    float p0 = g_probs[b*3+0], p1 = g_probs[b*3+1], p2 = g_probs[b*3+2];
    __shared__ float s[32][33];
    int c = threadIdx.x & 31, r = threadIdx.x >> 5;
#pragma unroll
    for (int rr = 0; rr < 4; rr++) {
        int k = k0 + r + 8 * rr;
        size_t o0 = (size_t)k * DD2 + (size_t)which * DD + j0 + c;
        s[r + 8*rr][c] = p0 * wgh[o0] + p1 * wgh[o0 + (size_t)DD*DD2] + p2 * wgh[o0 + (size_t)2*DD*DD2];
    }
    __syncthreads();
#pragma unroll
    for (int rr = 0; rr < 4; rr++) {
        int jl = r + 8 * rr, kl = c;
        size_t off = ((size_t)b * DD2 + 2*(j0+jl) + which) * DD + k0 + kl;
        g_wg[off] = __float2half_rn(s[kl][jl]);
    }
}

// ---------------- mix + transpose Wo -> fp16; b in fastest dim --------------------
__global__ void __launch_bounds__(256) k_mixoT(const float* __restrict__ wout) {
    int b = blockIdx.x & 7;
    int tile = blockIdx.x >> 3;
    int jt = tile & 31, kt2 = tile >> 5;
    int j0 = jt * 32, k0 = kt2 * 32;
    float p0 = g_probs[b*3+0], p1 = g_probs[b*3+1], p2 = g_probs[b*3+2];
    __shared__ float s[32][33];
    int c = threadIdx.x & 31, r = threadIdx.x >> 5;
#pragma unroll
    for (int rr = 0; rr < 4; rr++) {
        int k = k0 + r + 8 * rr;
        size_t o0 = (size_t)k * DD + j0 + c;
        s[r + 8*rr][c] = p0 * wout[o0] + p1 * wout[o0 + (size_t)DD*DD] + p2 * wout[o0 + (size_t)2*DD*DD];
    }
    __syncthreads();
#pragma unroll
    for (int rr = 0; rr < 4; rr++) {
        int jl = r + 8 * rr, kl = c;
        size_t off = ((size_t)b * DD + j0 + jl) * DD + k0 + kl;
        g_wo[off] = __float2half_rn(s[kl][jl]);
    }
}

// ---------------- GEMM1: hg = x @ Wg^T -> packed (a,b) + fused chunk-scan ---------
__global__ void __launch_bounds__(NT, 2) k_gemm1(const float* __restrict__ state) {
    extern __shared__ __align__(128) char smraw[];
    uint32_t sb = cvta_smem(smraw);
    int tid = threadIdx.x;
    int b = blockIdx.z, m0 = blockIdx.y * 128, n0 = blockIdx.x * 128;

    const __half* A = g_xh + ((size_t)b * SS  + m0) * DD;
    const __half* B = g_wg + ((size_t)b * DD2 + n0) * DD;

    float c[4][4][4];
#pragma unroll
    for (int i = 0; i < 4; i++)
#pragma unroll
        for (int j = 0; j < 4; j++)
#pragma unroll
            for (int k = 0; k < 4; k++) c[i][j][k] = 0.0f;

    gemm_mainloop(c, sb, A, B, tid);

    // stage packed (a,b) half2 into smem (128 rows x 64 j, pitch 68)
    uint32_t* sab = (uint32_t*)smraw;
    int lane = tid & 31, wid = tid >> 5;
    int wm = wid >> 2, wn = wid & 3;
    int rloc = wm * 64 + (lane >> 2);
    int jloc = wn * 16 + (lane & 3);
#pragma unroll
    for (int mf = 0; mf < 4; mf++)
#pragma unroll
        for (int nf = 0; nf < 4; nf++)
#pragma unroll
            for (int hh2 = 0; hh2 < 2; hh2++) {
                float hid  = c[mf][nf][hh2 * 2];
                float gate = c[mf][nf][hh2 * 2 + 1];
                float z  = sigm(gate);
                float gg = (hid >= 0.0f) ? (hid + 0.5f) : sigm(hid);
                int r = rloc + mf * 16 + hh2 * 8;
                int j = jloc + nf * 4;
                __half2 v = __floats2half2_rn(1.0f - z, z * gg);
                sab[r * 68 + j] = *(uint32_t*)&v;
            }
    __syncthreads();

    // coalesced g_ab write (2048 uint4 over 256 threads)
#pragma unroll
    for (int it = 0; it < 8; it++) {
        int idx = tid + it * NT;
        int row = idx >> 4, seg = idx & 15;
        size_t off = ((size_t)b * SS + m0 + row) * DD + (n0 >> 1) + seg * 4;
        uint4 v = *(uint4*)&sab[row * 68 + seg * 4];
        *(uint4*)&g_ab[off] = v;
    }

    // fused scanA: per-chunk (A,B) carries from smem (2 chunks x 64 d-pairs)
    if (tid < 128) {
        int chunk = tid >> 6, d = tid & 63;
        int cglob = (m0 >> 6) + chunk;
        int dglob = (n0 >> 1) + d;
        float Ac = 1.0f, Bc = 0.0f;
        const uint32_t* base = sab + chunk * 64 * 68 + d;
#pragma unroll 8
        for (int s = 0; s < CL; s++) {
            __half2 ab = *(const __half2*)&base[s * 68];
            float as = __low2float(ab);
            float bs = __high2float(ab);
            if (cglob == 0 && s == 0) bs += as * state[b * DD + dglob];
            Bc = fmaf(as, Bc, bs);
            Ac *= as;
        }
        int off = (b * NCH + cglob) * DD + dglob;
        g_cA[off] = Ac;
        g_cB[off] = Bc;
    }
}

// ---------------- GEMM2: out = h @ Wo^T + inputs ------------------------------------
__global__ void __launch_bounds__(NT, 2) k_gemm2(const float* __restrict__ inputs,
                                                 float* __restrict__ out) {
    extern __shared__ __align__(128) char smraw[];
    uint32_t sb = cvta_smem(smraw);
    int tid = threadIdx.x;
    int b = blockIdx.z, m0 = blockIdx.y * 128, n0 = blockIdx.x * 128;

    const __half* A = g_hh + ((size_t)b * SS + m0) * DD;
    const __half* B = g_wo + ((size_t)b * DD + n0) * DD;

    float c[4][4][4];
#pragma unroll
    for (int i = 0; i < 4; i++)
#pragma unroll
        for (int j = 0; j < 4; j++)
#pragma unroll
            for (int k = 0; k < 4; k++) c[i][j][k] = 0.0f;

    gemm_mainloop(c, sb, A, B, tid);

    int lane = tid & 31, wid = tid >> 5;
    int wm = wid >> 2, wn = wid & 3;
    int rbase = m0 + wm * 64 + (lane >> 2);
    int cbase = n0 + wn * 32 + (lane & 3) * 2;
#pragma unroll
    for (int mf = 0; mf < 4; mf++)
#pragma unroll
        for (int nf = 0; nf < 4; nf++)
#pragma unroll
            for (int hh2 = 0; hh2 < 2; hh2++) {
                int row = rbase + mf * 16 + hh2 * 8;
                int col = cbase + nf * 8;
                size_t off = ((size_t)b * SS + row) * DD + col;
                float2 iv = *(const float2*)&inputs[off];
                float2 ov;
                ov.x = c[mf][nf][hh2 * 2]     + iv.x;
                ov.y = c[mf][nf][hh2 * 2 + 1] + iv.y;
                *(float2*)&out[off] = ov;
            }
}

// ---------------- scan (B: chunk carries; C: apply + h fp16) -----------------------
__global__ void k_scanB() {
    int idx = blockIdx.x * 256 + threadIdx.x;
    int d = idx & (DD - 1);
    int b = idx >> 10;
    float h = 0.0f;
    for (int c = 0; c < NCH; c++) {
        int off = (b * NCH + c) * DD + d;
        float A = g_cA[off], Bc = g_cB[off];
        g_cB[off] = h;
        h = fmaf(A, h, Bc);
    }
}

__global__ void k_scanC(const float* __restrict__ state, float* out, int out_size) {
    int idx = blockIdx.x * 256 + threadIdx.x;
    int d = idx & (DD - 1);
    int c = (idx >> 10) & (NCH - 1);
    int b = idx >> 16;
    size_t base = (size_t)(b * SS + c * CL) * DD + d;
    float h = g_cB[idx];
#pragma unroll 8
    for (int s = 0; s < CL; s++) {
        __half2 ab = g_ab[base + (size_t)s * DD];
        float as = __low2float(ab);
        float bs = __high2float(ab);
        if (c == 0 && s == 0) bs += as * state[b * DD + d];
        h = fmaf(as, h, bs);
        g_hh[base + (size_t)s * DD] = __float2half_rn(h);
    }
    if (c == NCH - 1 && out_size >= BB*SS*DD + BB*DD)
        out[BB*SS*DD + b * DD + d] = h;
}

// ---------------- launch ------------------------------------------------------------
extern "C" void kernel_launch(void* const* d_in, const int* in_sizes, int n_in,
                              void* d_out, int out_size) {
    const float* inputs = (const float*)d_in[0];
    const float* state  = (const float*)d_in[1];
    const float* normw  = (const float*)d_in[2];
    const float* rw     = (const float*)d_in[3];
    const float* rb     = (const float*)d_in[4];
    const float* wgh    = (const float*)d_in[5];
    const float* wout   = (const float*)d_in[6];
    float* out = (float*)d_out;

    cudaFuncSetAttribute(k_gemm1, cudaFuncAttributeMaxDynamicSharedMemorySize, SMEM_BYTES);
    cudaFuncSetAttribute(k_gemm2, cudaFuncAttributeMaxDynamicSharedMemorySize, SMEM_BYTES);

    k_rmsnorm<<<dim3(SS / 64, BB), 256>>>(inputs, normw);
    k_router <<<BB, 128>>>(rw, rb, out, out_size);
    k_mixgT  <<<dim3(8192, 2), 256>>>(wgh);
    k_gemm1  <<<dim3(DD2 / 128, SS / 128, BB), NT, SMEM_BYTES>>>(state);
    k_mixoT  <<<dim3(8192, 1), 256>>>(wout);
    k_scanB  <<<(BB * DD) / 256, 256>>>();
    k_scanC  <<<(BB * NCH * DD) / 256, 256>>>(state, out, out_size);
    k_gemm2  <<<dim3(DD / 128, SS / 128, BB), NT, SMEM_BYTES>>>(inputs, out);
}

// round 11
// speedup vs baseline: 7.0729x; 1.0840x over previous
#include <cuda_runtime.h>
#include <cuda_fp16.h>
#include <cstdint>
#include <math.h>

#define BB   8
#define SS   4096
#define DD   1024
#define DD2  2048
#define CL   64
#define NCH  64
#define EPSV 1e-5f

// ---------------- scratch (device globals) -----------------------------------
__device__ __half g_xh[BB*SS*DD];                   // rmsnorm x fp16
__device__ __half g_wg[BB*DD2*DD];                  // mixed Wg^T (interleaved n) fp16
__device__ __half g_wo[BB*DD*DD];                   // mixed Wo^T fp16
__device__ __half g_hh[BB*SS*DD];                   // scan h fp16
__device__ __half2 g_ab[BB*SS*DD];                  // packed gates (a,b) fp16
__device__ float g_part[BB*64*DD];                  // per-block partial colsums
__device__ float g_probs [BB*3];
__device__ float g_cA[BB*NCH*DD], g_cB[BB*NCH*DD];

__device__ __forceinline__ float sigm(float x) { return 1.0f / (1.0f + __expf(-x)); }

__device__ __forceinline__ uint32_t cvta_smem(const void* p) {
    uint32_t a;
    asm("{ .reg .u64 t; cvta.to.shared.u64 t, %1; cvt.u32.u64 %0, t; }" : "=r"(a) : "l"(p));
    return a;
}

// ---------------- portable tensor-core primitives ------------------------------
__device__ __forceinline__ void mma16816(float* c, const uint32_t* a, const uint32_t* b) {
    asm volatile(
        "mma.sync.aligned.m16n8k16.row.col.f32.f16.f16.f32 "
        "{%0,%1,%2,%3},{%4,%5,%6,%7},{%8,%9},{%0,%1,%2,%3};"
        : "+f"(c[0]), "+f"(c[1]), "+f"(c[2]), "+f"(c[3])
        : "r"(a[0]), "r"(a[1]), "r"(a[2]), "r"(a[3]), "r"(b[0]), "r"(b[1]));
}
__device__ __forceinline__ void ldm4(uint32_t* r, uint32_t a) {
    asm volatile("ldmatrix.sync.aligned.m8n8.x4.shared.b16 {%0,%1,%2,%3}, [%4];"
        : "=r"(r[0]), "=r"(r[1]), "=r"(r[2]), "=r"(r[3]) : "r"(a));
}
#define CPA(s, g) asm volatile("cp.async.cg.shared.global [%0], [%1], 16;" :: "r"(s), "l"(g))
#define CP_COMMIT() asm volatile("cp.async.commit_group;")
#define CP_WAIT0()  asm volatile("cp.async.wait_group 0;")

#define NT 128     // threads per GEMM CTA (4 warps); 4 CTAs per SM

// smem stage (BK=64, 128B rows, XOR-swizzled): A 64x128B | B 128x128B ; 2 stages
#define A_BYTES    8192
#define STAGE_B    24576
#define SMEM_BYTES 49152

// swizzled byte offset within a matrix: row r (128B rows), 16B-chunk cc
#define SWZ(r, cc) ((r) * 128 + (((cc) ^ ((r) & 7)) << 4))

template<int ROWS>
__device__ __forceinline__ void load_mat(uint32_t sdst, const __half* g, int tid) {
#pragma unroll
    for (int it = 0; it < ROWS * 8 / NT; it++) {
        int idx = tid + it * NT;
        int r = idx >> 3, cc = idx & 7;
        CPA(sdst + SWZ(r, cc), g + (size_t)r * DD + cc * 8);
    }
}
__device__ __forceinline__ void load_stage(uint32_t sbuf,
    const __half* A, const __half* B, int k0, int tid) {
    load_mat<64> (sbuf,           A + k0, tid);
    load_mat<128>(sbuf + A_BYTES, B + k0, tid);
}

// 64x128 CTA tile, 4 warps (1M x 4N), warp tile 64x32; fp16, BK=64, 2-stage pipe.
__device__ __forceinline__ void gemm_mainloop(
    float c[4][4][4], uint32_t sb,
    const __half* A, const __half* B, int tid) {

    int lane = tid & 31, wid = tid >> 5;
    int wn = wid;                                        // warp grid 1M x 4N
    int ra = lane & 15;                                  // A row (mf adds 16)
    int rb = wn * 32 + (lane & 7) + ((lane >> 4) << 3);  // B row (ng adds 16)
    int ca0 = lane >> 4;                                 // A chunk base (ks adds 2)
    int cb0 = (lane >> 3) & 1;                           // B chunk base (ks adds 2)

    load_stage(sb, A, B, 0, tid); CP_COMMIT();

#pragma unroll 1
    for (int s = 0; s < 16; s++) {
        CP_WAIT0();
        __syncthreads();
        if (s < 15) {
            load_stage(sb + ((s + 1) & 1) * STAGE_B, A, B, (s + 1) * 64, tid);
            CP_COMMIT();
        }
        uint32_t base  = sb + (s & 1) * STAGE_B;
        uint32_t baseB = base + A_BYTES;
#pragma unroll
        for (int ks = 0; ks < 4; ks++) {
            uint32_t ah[4][4], bh[2][4];
#pragma unroll
            for (int mf = 0; mf < 4; mf++)
                ldm4(ah[mf], base + SWZ(ra + mf * 16, ca0 + ks * 2));
#pragma unroll
            for (int ng = 0; ng < 2; ng++)
                ldm4(bh[ng], baseB + SWZ(rb + ng * 16, cb0 + ks * 2));
#pragma unroll
            for (int mf = 0; mf < 4; mf++)
#pragma unroll
                for (int nf = 0; nf < 4; nf++)
                    mma16816(c[mf][nf], ah[mf], &bh[nf >> 1][(nf & 1) * 2]);
        }
    }
    __syncthreads();
}

// ---------------- rmsnorm -> fp16 + per-block partial colsum ---------------------
__global__ void __launch_bounds__(256) k_rmsnorm(const float* __restrict__ inp,
                                                 const float* __restrict__ normw) {
    int b = blockIdx.y, t = threadIdx.x, warp = t >> 5, lane = t & 31;
    __shared__ float sw[DD];
    __shared__ float scs[DD];
    for (int i = t; i < DD; i += 256) { sw[i] = normw[i]; scs[i] = 0.0f; }
    __syncthreads();
    float csum[32];
#pragma unroll
    for (int k = 0; k < 32; k++) csum[k] = 0.0f;
    int s_base = blockIdx.x * 64;
#pragma unroll 1
    for (int r = 0; r < 8; r++) {
        int s = s_base + warp + r * 8;
        const float* row = inp + (size_t)(b * SS + s) * DD;
        float v[32], ss = 0.0f;
#pragma unroll
        for (int k = 0; k < 32; k++) { v[k] = row[lane + 32 * k]; ss += v[k] * v[k]; }
#pragma unroll
        for (int o = 16; o > 0; o >>= 1) ss += __shfl_xor_sync(0xffffffffu, ss, o);
        float inv = rsqrtf(ss * (1.0f / DD) + EPSV);
        size_t ro = (size_t)(b * SS + s) * DD;
#pragma unroll
        for (int k = 0; k < 32; k++) {
            float xv = v[k] * inv * sw[lane + 32 * k];
            g_xh[ro + lane + 32 * k] = __float2half_rn(xv);
            csum[k] += xv;
        }
    }
#pragma unroll
    for (int k = 0; k < 32; k++) atomicAdd(&scs[lane + 32 * k], csum[k]);
    __syncthreads();
    for (int i = t; i < DD; i += 256)
        g_part[((size_t)b * 64 + blockIdx.x) * DD + i] = scs[i];
}

// ---------------- router (reduces partials) + aux_loss ----------------------------
__global__ void k_router(const float* __restrict__ rw, const float* __restrict__ rb,
                         float* out, int out_size) {
    int b = blockIdx.x, t = threadIdx.x;
    if (b == 0 && t == 0 && out_size >= BB*SS*DD + BB*DD + 1)
        out[BB*SS*DD + BB*DD] = 0.0f;
    float p0 = 0, p1 = 0, p2 = 0;
    for (int d = t; d < DD; d += 128) {
        float cs = 0.0f;
        for (int blk = 0; blk < 64; blk++)
            cs += g_part[((size_t)b * 64 + blk) * DD + d];
        cs *= (1.0f / SS);
        p0 += cs * rw[d * 3 + 0];
        p1 += cs * rw[d * 3 + 1];
        p2 += cs * rw[d * 3 + 2];
    }
    __shared__ float sm[3][128];
    sm[0][t] = p0; sm[1][t] = p1; sm[2][t] = p2;
    __syncthreads();
    for (int o = 64; o > 0; o >>= 1) {
        if (t < o) { sm[0][t] += sm[0][t+o]; sm[1][t] += sm[1][t+o]; sm[2][t] += sm[2][t+o]; }
        __syncthreads();
    }
    if (t == 0) {
        float l0 = sm[0][0] + rb[0], l1 = sm[1][0] + rb[1], l2 = sm[2][0] + rb[2];
        float m = fmaxf(l0, fmaxf(l1, l2));
        float e0 = __expf(l0-m), e1 = __expf(l1-m), e2 = __expf(l2-m);
        float inv = 1.0f / (e0 + e1 + e2);
        g_probs[b*3+0] = e0*inv; g_probs[b*3+1] = e1*inv; g_probs[b*3+2] = e2*inv;
    }
}

// ---------------- mix + transpose Wg (interleaved n) -> fp16; b in fastest dim ---
__global__ void __launch_bounds__(256) k_mixgT(const float* __restrict__ wgh) {
    int b = blockIdx.x & 7;
    int tile = blockIdx.x >> 3;
    int which = blockIdx.y;
    int jt = tile & 31, kt2 = tile >> 5;
    int j0 = jt * 32, k0 = kt2 * 32;
    float p0 = g_probs[b*3+0], p1 = g_probs[b*3+1], p2 = g_probs[b*3+2];
    __shared__ float s[32][33];
    int c = threadIdx.x & 31, r = threadIdx.x >> 5;
#pragma unroll
    for (int rr = 0; rr < 4; rr++) {
        int k = k0 + r + 8 * rr;
        size_t o0 = (size_t)k * DD2 + (size_t)which * DD + j0 + c;
        s[r + 8*rr][c] = p0 * wgh[o0] + p1 * wgh[o0 + (size_t)DD*DD2] + p2 * wgh[o0 + (size_t)2*DD*DD2];
    }
    __syncthreads();
#pragma unroll
    for (int rr = 0; rr < 4; rr++) {
        int jl = r + 8 * rr, kl = c;
        size_t off = ((size_t)b * DD2 + 2*(j0+jl) + which) * DD + k0 + kl;
        g_wg[off] = __float2half_rn(s[kl][jl]);
    }
}

// ---------------- mix + transpose Wo -> fp16; b in fastest dim --------------------
__global__ void __launch_bounds__(256) k_mixoT(const float* __restrict__ wout) {
    int b = blockIdx.x & 7;
    int tile = blockIdx.x >> 3;
    int jt = tile & 31, kt2 = tile >> 5;
    int j0 = jt * 32, k0 = kt2 * 32;
    float p0 = g_probs[b*3+0], p1 = g_probs[b*3+1], p2 = g_probs[b*3+2];
    __shared__ float s[32][33];
    int c = threadIdx.x & 31, r = threadIdx.x >> 5;
#pragma unroll
    for (int rr = 0; rr < 4; rr++) {
        int k = k0 + r + 8 * rr;
        size_t o0 = (size_t)k * DD + j0 + c;
        s[r + 8*rr][c] = p0 * wout[o0] + p1 * wout[o0 + (size_t)DD*DD] + p2 * wout[o0 + (size_t)2*DD*DD];
    }
    __syncthreads();
#pragma unroll
    for (int rr = 0; rr < 4; rr++) {
        int jl = r + 8 * rr, kl = c;
        size_t off = ((size_t)b * DD + j0 + jl) * DD + k0 + kl;
        g_wo[off] = __float2half_rn(s[kl][jl]);
    }
}

// ---------------- GEMM1: hg = x @ Wg^T -> packed (a,b) + fused chunk-scan ---------
__global__ void __launch_bounds__(NT, 4) k_gemm1(const float* __restrict__ state) {
    extern __shared__ __align__(128) char smraw[];
    uint32_t sb = cvta_smem(smraw);
    int tid = threadIdx.x;
    int b = blockIdx.z, m0 = blockIdx.y * 64, n0 = blockIdx.x * 128;

    const __half* A = g_xh + ((size_t)b * SS  + m0) * DD;
    const __half* B = g_wg + ((size_t)b * DD2 + n0) * DD;

    float c[4][4][4];
#pragma unroll
    for (int i = 0; i < 4; i++)
#pragma unroll
        for (int j = 0; j < 4; j++)
#pragma unroll
            for (int k = 0; k < 4; k++) c[i][j][k] = 0.0f;

    gemm_mainloop(c, sb, A, B, tid);

    // stage packed (a,b) half2 into smem (64 rows x 64 j, pitch 68)
    uint32_t* sab = (uint32_t*)smraw;
    int lane = tid & 31, wid = tid >> 5;
    int wn = wid;
    int rloc = lane >> 2;
    int jloc = wn * 16 + (lane & 3);
#pragma unroll
    for (int mf = 0; mf < 4; mf++)
#pragma unroll
        for (int nf = 0; nf < 4; nf++)
#pragma unroll
            for (int hh2 = 0; hh2 < 2; hh2++) {
                float hid  = c[mf][nf][hh2 * 2];
                float gate = c[mf][nf][hh2 * 2 + 1];
                float z  = sigm(gate);
                float gg = (hid >= 0.0f) ? (hid + 0.5f) : sigm(hid);
                int r = rloc + mf * 16 + hh2 * 8;
                int j = jloc + nf * 4;
                __half2 v = __floats2half2_rn(1.0f - z, z * gg);
                sab[r * 68 + j] = *(uint32_t*)&v;
            }
    __syncthreads();

    // coalesced g_ab write (1024 uint4 over 128 threads)
#pragma unroll
    for (int it = 0; it < 8; it++) {
        int idx = tid + it * NT;
        int row = idx >> 4, seg = idx & 15;
        size_t off = ((size_t)b * SS + m0 + row) * DD + (n0 >> 1) + seg * 4;
        uint4 v = *(uint4*)&sab[row * 68 + seg * 4];
        *(uint4*)&g_ab[off] = v;
    }

    // fused scanA: per-chunk (A,B) carries from smem (1 chunk x 64 d-pairs)
    if (tid < 64) {
        int d = tid;
        int cglob = blockIdx.y;                 // chunk index (tile M == CL)
        int dglob = (n0 >> 1) + d;
        float Ac = 1.0f, Bc = 0.0f;
        const uint32_t* base = sab + d;
#pragma unroll 8
        for (int s = 0; s < CL; s++) {
            __half2 ab = *(const __half2*)&base[s * 68];
            float as = __low2float(ab);
            float bs = __high2float(ab);
            if (cglob == 0 && s == 0) bs += as * state[b * DD + dglob];
            Bc = fmaf(as, Bc, bs);
            Ac *= as;
        }
        int off = (b * NCH + cglob) * DD + dglob;
        g_cA[off] = Ac;
        g_cB[off] = Bc;
    }
}

// ---------------- GEMM2: out = h @ Wo^T + inputs ------------------------------------
__global__ void __launch_bounds__(NT, 4) k_gemm2(const float* __restrict__ inputs,
                                                 float* __restrict__ out) {
    extern __shared__ __align__(128) char smraw[];
    uint32_t sb = cvta_smem(smraw);
    int tid = threadIdx.x;
    int b = blockIdx.z, m0 = blockIdx.y * 64, n0 = blockIdx.x * 128;

    const __half* A = g_hh + ((size_t)b * SS + m0) * DD;
    const __half* B = g_wo + ((size_t)b * DD + n0) * DD;

    float c[4][4][4];
#pragma unroll
    for (int i = 0; i < 4; i++)
#pragma unroll
        for (int j = 0; j < 4; j++)
#pragma unroll
            for (int k = 0; k < 4; k++) c[i][j][k] = 0.0f;

    gemm_mainloop(c, sb, A, B, tid);

    int lane = tid & 31, wid = tid >> 5;
    int wn = wid;
    int rbase = m0 + (lane >> 2);
    int cbase = n0 + wn * 32 + (lane & 3) * 2;
#pragma unroll
    for (int mf = 0; mf < 4; mf++)
#pragma unroll
        for (int nf = 0; nf < 4; nf++)
#pragma unroll
            for (int hh2 = 0; hh2 < 2; hh2++) {
                int row = rbase + mf * 16 + hh2 * 8;
                int col = cbase + nf * 8;
                size_t off = ((size_t)b * SS + row) * DD + col;
                float2 iv = *(const float2*)&inputs[off];
                float2 ov;
                ov.x = c[mf][nf][hh2 * 2]     + iv.x;
                ov.y = c[mf][nf][hh2 * 2 + 1] + iv.y;
                *(float2*)&out[off] = ov;
            }
}

// ---------------- scan (B: chunk carries; C: apply + h fp16) -----------------------
__global__ void k_scanB() {
    int idx = blockIdx.x * 256 + threadIdx.x;
    int d = idx & (DD - 1);
    int b = idx >> 10;
    float h = 0.0f;
    for (int c = 0; c < NCH; c++) {
        int off = (b * NCH + c) * DD + d;
        float A = g_cA[off], Bc = g_cB[off];
        g_cB[off] = h;
        h = fmaf(A, h, Bc);
    }
}

__global__ void k_scanC(const float* __restrict__ state, float* out, int out_size) {
    int idx = blockIdx.x * 256 + threadIdx.x;
    int d = idx & (DD - 1);
    int c = (idx >> 10) & (NCH - 1);
    int b = idx >> 16;
    size_t base = (size_t)(b * SS + c * CL) * DD + d;
    float h = g_cB[idx];
#pragma unroll 8
    for (int s = 0; s < CL; s++) {
        __half2 ab = g_ab[base + (size_t)s * DD];
        float as = __low2float(ab);
        float bs = __high2float(ab);
        if (c == 0 && s == 0) bs += as * state[b * DD + d];
        h = fmaf(as, h, bs);
        g_hh[base + (size_t)s * DD] = __float2half_rn(h);
    }
    if (c == NCH - 1 && out_size >= BB*SS*DD + BB*DD)
        out[BB*SS*DD + b * DD + d] = h;
}

// ---------------- launch ------------------------------------------------------------
extern "C" void kernel_launch(void* const* d_in, const int* in_sizes, int n_in,
                              void* d_out, int out_size) {
    const float* inputs = (const float*)d_in[0];
    const float* state  = (const float*)d_in[1];
    const float* normw  = (const float*)d_in[2];
    const float* rw     = (const float*)d_in[3];
    const float* rb     = (const float*)d_in[4];
    const float* wgh    = (const float*)d_in[5];
    const float* wout   = (const float*)d_in[6];
    float* out = (float*)d_out;

    cudaFuncSetAttribute(k_gemm1, cudaFuncAttributeMaxDynamicSharedMemorySize, SMEM_BYTES);
    cudaFuncSetAttribute(k_gemm2, cudaFuncAttributeMaxDynamicSharedMemorySize, SMEM_BYTES);

    k_rmsnorm<<<dim3(SS / 64, BB), 256>>>(inputs, normw);
    k_router <<<BB, 128>>>(rw, rb, out, out_size);
    k_mixgT  <<<dim3(8192, 2), 256>>>(wgh);
    k_gemm1  <<<dim3(DD2 / 128, SS / 64, BB), NT, SMEM_BYTES>>>(state);
    k_mixoT  <<<dim3(8192, 1), 256>>>(wout);
    k_scanB  <<<(BB * DD) / 256, 256>>>();
    k_scanC  <<<(BB * NCH * DD) / 256, 256>>>(state, out, out_size);
    k_gemm2  <<<dim3(DD / 128, SS / 64, BB), NT, SMEM_BYTES>>>(inputs, out);
}